// round 6
// baseline (speedup 1.0000x reference)
#include <cuda_runtime.h>
#include <cuda_bf16.h>

// Problem constants
#define T_TOK   32768
#define B_SEG   8
#define H_HEAD  8
#define D_DIM   128
#define HD      (H_HEAD * D_DIM)   // 1024 floats per token row

// Fused-kernel geometry
#define NBLK    512                // total blocks (all do segsum)
#define TPB     256
#define TOKS    (T_TOK / NBLK)     // 64 tokens per block
#define NB_MLP  16                 // blocks that continue into the MLP

// Scratch (device globals — zero-initialized at module load; g_sums and g_bar
// are restored to zero by block 0 at the END of every call, so the entry
// invariant (all zero) holds on every graph replay deterministically).
__device__ float    g_sums[B_SEG * D_DIM];
__device__ float    g_h1[B_SEG * 1024];
__device__ float    g_p2[NB_MLP * B_SEG * 256];
__device__ float    g_h3[B_SEG * 512];
__device__ float    g_p4[NB_MLP * B_SEG * 128];
__device__ unsigned g_bar[5];

__device__ __forceinline__ float silu_f(float x) {
    return x / (1.0f + __expf(-x));
}

// Arrive: make this block's global writes visible, then count in.
__device__ __forceinline__ void bar_arrive(int i) {
    __threadfence();
    __syncthreads();
    if (threadIdx.x == 0) atomicAdd(&g_bar[i], 1u);
}
// Wait until all NBLK blocks have arrived at counter i.
__device__ __forceinline__ void bar_wait(int i) {
    if (threadIdx.x == 0) {
        volatile unsigned* p = &g_bar[i];
        while (*p < NBLK) __nanosleep(64);
    }
    __syncthreads();
    __threadfence();
}

// ---------------------------------------------------------------------------
// Single fused kernel: segment+head sum  ->  5-layer MLP  ->  hard routing
// ---------------------------------------------------------------------------
__global__ __launch_bounds__(TPB) void fused_all_kernel(
    const float4* __restrict__ x, const int* __restrict__ cu,
    const float* __restrict__ w1, const float* __restrict__ b1,
    const float* __restrict__ w2, const float* __restrict__ b2,
    const float* __restrict__ w3, const float* __restrict__ b3,
    const float* __restrict__ w4, const float* __restrict__ b4,
    const float* __restrict__ w5, const float* __restrict__ b5,
    float* __restrict__ out)
{
    __shared__ float sm[2048];          // aliased per phase (max: L5 = 2048)
    __shared__ int   touched[B_SEG];

    const int tid = threadIdx.x;
    const int bid = blockIdx.x;

    // ======================= Phase A: segsum ===============================
    // g_sums[b][d] = sum_{t in seg b} sum_h x[t,h,d].  Block owns 64 rows.
    {
        float* ssum = sm;               // [8][128]
        for (int i = tid; i < B_SEG * D_DIM; i += TPB) ssum[i] = 0.0f;
        if (tid < B_SEG) touched[tid] = 0;
        __syncthreads();

        const int c1 = cu[1], c2 = cu[2], c3 = cu[3], c4 = cu[4];
        const int c5 = cu[5], c6 = cu[6], c7 = cu[7];

        const int t0    = bid * TOKS;
        const int dbase = (4 * tid) & (D_DIM - 1);

        // seg = #inner boundaries <= t (matches searchsorted 'right' - 1,
        // incl. duplicate-boundary / empty-segment cases)
        #define SEGOF(t) ((int)(((t) >= c1) + ((t) >= c2) + ((t) >= c3) + \
                                ((t) >= c4) + ((t) >= c5) + ((t) >= c6) + \
                                ((t) >= c7)))

        const int seg_lo = SEGOF(t0);
        const int seg_hi = SEGOF(t0 + TOKS - 1);

        if (seg_lo == seg_hi) {
            // FAST PATH (>= 505/512 blocks): no boundary inside this block.
            // Branch-free batched loads -> ptxas front-batches 8 LDG.128s,
            // MLP_eff ~ 8, stream runs at the HBM roofline.
            const float4* px = x + (size_t)t0 * (HD / 4) + tid;
            float a0 = 0.f, a1 = 0.f, a2 = 0.f, a3 = 0.f;
            #pragma unroll 1
            for (int g = 0; g < TOKS; g += 8) {
                float4 v[8];
                #pragma unroll
                for (int u = 0; u < 8; u++)
                    v[u] = __ldcs(px + (size_t)(g + u) * (HD / 4));
                #pragma unroll
                for (int u = 0; u < 8; u++) {
                    a0 += v[u].x; a1 += v[u].y; a2 += v[u].z; a3 += v[u].w;
                }
            }
            atomicAdd(&ssum[seg_lo * D_DIM + dbase + 0], a0);
            atomicAdd(&ssum[seg_lo * D_DIM + dbase + 1], a1);
            atomicAdd(&ssum[seg_lo * D_DIM + dbase + 2], a2);
            atomicAdd(&ssum[seg_lo * D_DIM + dbase + 3], a3);
            if (tid == 0) touched[seg_lo] = 1;
        } else {
            // SLOW PATH (boundary blocks, <= 7 of 512): per-token seg walk.
            float a0 = 0.f, a1 = 0.f, a2 = 0.f, a3 = 0.f;
            int curseg = -1;
            for (int tt = 0; tt < TOKS; tt++) {
                const int t = t0 + tt;
                const int seg = SEGOF(t);
                if (seg != curseg) {    // block-uniform branch
                    if (curseg >= 0) {
                        atomicAdd(&ssum[curseg * D_DIM + dbase + 0], a0);
                        atomicAdd(&ssum[curseg * D_DIM + dbase + 1], a1);
                        atomicAdd(&ssum[curseg * D_DIM + dbase + 2], a2);
                        atomicAdd(&ssum[curseg * D_DIM + dbase + 3], a3);
                        touched[curseg] = 1;
                    }
                    curseg = seg;
                    a0 = a1 = a2 = a3 = 0.f;
                }
                float4 v = __ldcs(&x[(size_t)t * (HD / 4) + tid]);
                a0 += v.x; a1 += v.y; a2 += v.z; a3 += v.w;
            }
            if (curseg >= 0) {
                atomicAdd(&ssum[curseg * D_DIM + dbase + 0], a0);
                atomicAdd(&ssum[curseg * D_DIM + dbase + 1], a1);
                atomicAdd(&ssum[curseg * D_DIM + dbase + 2], a2);
                atomicAdd(&ssum[curseg * D_DIM + dbase + 3], a3);
                touched[curseg] = 1;
            }
        }
        #undef SEGOF
        __syncthreads();

        for (int s = 0; s < B_SEG; s++) {
            if (touched[s]) {
                for (int i = tid; i < D_DIM; i += TPB)
                    atomicAdd(&g_sums[s * D_DIM + i], ssum[s * D_DIM + i]);
            }
        }
    }

    // ======================= Barrier / early exit ==========================
    if (bid >= NB_MLP) {
        // Arrive at ALL barriers, then leave. Never spins -> no deadlock,
        // SMs drain immediately.
        __threadfence();
        __syncthreads();
        if (tid == 0) {
            atomicAdd(&g_bar[0], 1u);
            atomicAdd(&g_bar[1], 1u);
            atomicAdd(&g_bar[2], 1u);
            atomicAdd(&g_bar[3], 1u);
            atomicAdd(&g_bar[4], 1u);
        }
        return;
    }

    bar_arrive(0);
    bar_wait(0);

    const int gt = bid * TPB + tid;     // 0..4095 over the 16 MLP blocks

    // ===== L1: pooled(8x128) -> h1(8x1024), silu ===========================
    {
        float* s_pool = sm;             // [8][128]
        __syncthreads();
        for (int i = tid; i < B_SEG * D_DIM; i += TPB) {
            const int b = i >> 7;
            const int cnt = cu[b + 1] - cu[b];
            const float c = (float)(cnt > 1 ? cnt : 1);
            s_pool[i] = g_sums[i] * (1.0f / (8.0f * c));
        }
        __syncthreads();

        const int j  = gt & 1023;
        const int b0 = (gt >> 10) << 1;     // 0,2,4,6
        const float* p0 = &s_pool[b0 * 128];
        const float* p1 = &s_pool[b0 * 128 + 128];
        float acc0 = b1[j], acc1 = b1[j];
        #pragma unroll 8
        for (int k = 0; k < 128; k++) {
            const float w = w1[k * 1024 + j];
            acc0 += p0[k] * w;
            acc1 += p1[k] * w;
        }
        g_h1[(b0 + 0) * 1024 + j] = silu_f(acc0);
        g_h1[(b0 + 1) * 1024 + j] = silu_f(acc1);
    }
    bar_arrive(1);
    bar_wait(1);

    // ===== L2: h1(8x1024) -> partials(16 x 8 x 256) ========================
    {
        float* s_in = sm;               // [8][64]
        __syncthreads();
        for (int i = tid; i < B_SEG * 64; i += TPB) {
            const int b = i >> 6;
            const int k = i & 63;
            s_in[i] = g_h1[b * 1024 + bid * 64 + k];
        }
        __syncthreads();

        const int j = tid;
        float acc[B_SEG];
        #pragma unroll
        for (int b = 0; b < B_SEG; b++) acc[b] = 0.0f;
        #pragma unroll 4
        for (int k = 0; k < 64; k++) {
            const float w = w2[(bid * 64 + k) * 256 + j];
            #pragma unroll
            for (int b = 0; b < B_SEG; b++)
                acc[b] += s_in[b * 64 + k] * w;
        }
        #pragma unroll
        for (int b = 0; b < B_SEG; b++)
            g_p2[(bid * B_SEG + b) * 256 + j] = acc[b];
    }
    bar_arrive(2);
    bar_wait(2);

    // ===== L3: h2(8x256) -> h3(8x512), silu ================================
    {
        float* s_h2 = sm;               // [256]
        const int b = bid >> 1;
        __syncthreads();
        {
            const int k = tid;
            float v = b2[k];
            #pragma unroll
            for (int c = 0; c < NB_MLP; c++)
                v += g_p2[(c * B_SEG + b) * 256 + k];
            s_h2[k] = v;
        }
        __syncthreads();

        const int j = ((bid & 1) << 8) + tid;
        float acc = b3[j];
        #pragma unroll 8
        for (int k = 0; k < 256; k++)
            acc += s_h2[k] * w3[k * 512 + j];
        g_h3[b * 512 + j] = silu_f(acc);
    }
    bar_arrive(3);
    bar_wait(3);

    // ===== L4: h3(8x512) -> partials(16 x 8 x 128), silu deferred ==========
    {
        float* s_in = sm;               // [8][32]
        __syncthreads();
        for (int i = tid; i < B_SEG * 32; i += TPB) {
            const int b = i >> 5;
            const int k = i & 31;
            s_in[i] = g_h3[b * 512 + bid * 32 + k];
        }
        __syncthreads();

        const int j  = tid & 127;
        const int bh = tid >> 7;        // 0 or 1
        float acc[4];
        #pragma unroll
        for (int i = 0; i < 4; i++) acc[i] = 0.0f;
        #pragma unroll 4
        for (int k = 0; k < 32; k++) {
            const float w = w4[(bid * 32 + k) * 128 + j];
            #pragma unroll
            for (int i = 0; i < 4; i++)
                acc[i] += s_in[(bh * 4 + i) * 32 + k] * w;
        }
        #pragma unroll
        for (int i = 0; i < 4; i++)
            g_p4[(bid * B_SEG + bh * 4 + i) * 128 + j] = acc[i];
    }
    bar_arrive(4);                      // blocks 1..15 arrive and exit
    if (bid != 0) return;
    bar_wait(4);                        // ONLY block 0 ever waits here

    // ===== L5 (block 0): logits + hard routing =============================
    {
        float* sred0 = sm;              // [8][128]
        float* sred1 = sm + 1024;       // [8][128]
        const int k  = tid & 127;
        const int bh = tid >> 7;        // batches {bh, bh+2, bh+4, bh+6}
        const float wa = w5[k * 2 + 0];
        const float wb = w5[k * 2 + 1];
        const float bias4 = b4[k];

        __syncthreads();
        #pragma unroll
        for (int i = 0; i < 4; i++) {
            const int b = bh + 2 * i;
            float v = bias4;
            #pragma unroll
            for (int c = 0; c < NB_MLP; c++)
                v += g_p4[(c * B_SEG + b) * 128 + k];
            const float s = silu_f(v);
            sred0[b * 128 + k] = s * wa;
            sred1[b * 128 + k] = s * wb;
        }
        __syncthreads();

        for (int off = 64; off >= 1; off >>= 1) {
            if (k < off) {
                #pragma unroll
                for (int i = 0; i < 4; i++) {
                    const int b = bh + 2 * i;
                    sred0[b * 128 + k] += sred0[b * 128 + k + off];
                    sred1[b * 128 + k] += sred1[b * 128 + k + off];
                }
            }
            __syncthreads();
        }

        if (k == 0) {
            const float bz0 = b5[0], bz1 = b5[1];
            #pragma unroll
            for (int i = 0; i < 4; i++) {
                const int b = bh + 2 * i;
                const float l0 = sred0[b * 128] + bz0;
                const float l1 = sred1[b * 128] + bz1;
                const float z  = (l1 > l0) ? 1.0f : 0.0f;
                #pragma unroll
                for (int h = 0; h < H_HEAD; h++)
                    out[b * H_HEAD + h] = z;
            }
        }
    }

    // ===== Restore entry invariants for the next call ======================
    // Safe: every other block has arrived at every barrier (bar4 count hit
    // NBLK), and only block 0 ever spins on bar4 — nobody else is reading
    // g_bar or g_sums anymore.
    __syncthreads();
    for (int i = tid; i < B_SEG * D_DIM; i += TPB) g_sums[i] = 0.0f;
    if (tid < 5) g_bar[tid] = 0u;
}

// ---------------------------------------------------------------------------
// Launch: ONE graph node
// ---------------------------------------------------------------------------
extern "C" void kernel_launch(void* const* d_in, const int* in_sizes, int n_in,
                              void* d_out, int out_size)
{
    const float* x  = (const float*)d_in[0];
    const int*   cu = (const int*)  d_in[1];
    const float* w1 = (const float*)d_in[2];
    const float* b1 = (const float*)d_in[3];
    const float* w2 = (const float*)d_in[4];
    const float* b2 = (const float*)d_in[5];
    const float* w3 = (const float*)d_in[6];
    const float* b3 = (const float*)d_in[7];
    const float* w4 = (const float*)d_in[8];
    const float* b4 = (const float*)d_in[9];
    const float* w5 = (const float*)d_in[10];
    const float* b5 = (const float*)d_in[11];
    float* out = (float*)d_out;

    fused_all_kernel<<<NBLK, TPB>>>((const float4*)x, cu,
                                    w1, b1, w2, b2, w3, b3, w4, b4, w5, b5, out);
}

// round 7
// speedup vs baseline: 1.2412x; 1.2412x over previous
#include <cuda_runtime.h>
#include <cuda_bf16.h>

// Problem constants
#define T_TOK   32768
#define B_SEG   8
#define H_HEAD  8
#define D_DIM   128
#define HD      (H_HEAD * D_DIM)   // 1024 floats per token row

// Fused-kernel geometry
#define NBLK    2048               // total blocks (all do segsum)
#define TPB     256
#define TOKS    (T_TOK / NBLK)     // 16 tokens per block
#define NB_MLP  16                 // blocks that continue into the MLP

// Scratch (device globals — zero-initialized at module load; g_sums and g_bar
// are restored to zero by block 0 at the END of every call, so the entry
// invariant (all zero) holds on every graph replay deterministically).
__device__ float    g_sums[B_SEG * D_DIM];
__device__ float    g_h1[B_SEG * 1024];
__device__ float    g_p2[NB_MLP * B_SEG * 256];
__device__ float    g_h3[B_SEG * 512];
__device__ float    g_p4[NB_MLP * B_SEG * 128];
__device__ unsigned g_bar[5];

__device__ __forceinline__ float silu_f(float x) {
    return x / (1.0f + __expf(-x));
}

// Arrive: make this block's global writes visible, then count in.
__device__ __forceinline__ void bar_arrive(int i) {
    __threadfence();
    __syncthreads();
    if (threadIdx.x == 0) atomicAdd(&g_bar[i], 1u);
}
// Wait until all NBLK blocks have arrived at counter i.
__device__ __forceinline__ void bar_wait(int i) {
    if (threadIdx.x == 0) {
        volatile unsigned* p = &g_bar[i];
        while (*p < NBLK) __nanosleep(64);
    }
    __syncthreads();
    __threadfence();
}

// ---------------------------------------------------------------------------
// Single fused kernel: segment+head sum  ->  5-layer MLP  ->  hard routing
// ---------------------------------------------------------------------------
__global__ __launch_bounds__(TPB) void fused_all_kernel(
    const float4* __restrict__ x, const int* __restrict__ cu,
    const float* __restrict__ w1, const float* __restrict__ b1,
    const float* __restrict__ w2, const float* __restrict__ b2,
    const float* __restrict__ w3, const float* __restrict__ b3,
    const float* __restrict__ w4, const float* __restrict__ b4,
    const float* __restrict__ w5, const float* __restrict__ b5,
    float* __restrict__ out)
{
    __shared__ float sm[2048];          // aliased per phase (max: L5 = 2048)
    __shared__ int   touched[B_SEG];

    const int tid = threadIdx.x;
    const int bid = blockIdx.x;

    // ======================= Phase A: segsum ===============================
    // g_sums[b][d] = sum_{t in seg b} sum_h x[t,h,d].  Block owns 16 rows.
    {
        float* ssum = sm;               // [8][128]
        for (int i = tid; i < B_SEG * D_DIM; i += TPB) ssum[i] = 0.0f;
        if (tid < B_SEG) touched[tid] = 0;
        __syncthreads();

        const int c1 = cu[1], c2 = cu[2], c3 = cu[3], c4 = cu[4];
        const int c5 = cu[5], c6 = cu[6], c7 = cu[7];

        const int t0    = bid * TOKS;
        const int dbase = (4 * tid) & (D_DIM - 1);

        // seg = #inner boundaries <= t (matches searchsorted 'right' - 1,
        // incl. duplicate-boundary / empty-segment cases)
        #define SEGOF(t) ((int)(((t) >= c1) + ((t) >= c2) + ((t) >= c3) + \
                                ((t) >= c4) + ((t) >= c5) + ((t) >= c6) + \
                                ((t) >= c7)))

        const int seg_lo = SEGOF(t0);
        const int seg_hi = SEGOF(t0 + TOKS - 1);

        if (seg_lo == seg_hi) {
            // FAST PATH (>= 2041/2048 blocks): no boundary in this block.
            // Branch-free; 4 loads per batch (unroll 1 keeps regs ~44 so
            // ~5 blocks/SM stay resident — occupancy does the latency hiding).
            const float4* px = x + (size_t)t0 * (HD / 4) + tid;
            float a0 = 0.f, a1 = 0.f, a2 = 0.f, a3 = 0.f;
            #pragma unroll 1
            for (int g = 0; g < TOKS; g += 4) {
                float4 v0 = __ldcs(px + (size_t)(g + 0) * (HD / 4));
                float4 v1 = __ldcs(px + (size_t)(g + 1) * (HD / 4));
                float4 v2 = __ldcs(px + (size_t)(g + 2) * (HD / 4));
                float4 v3 = __ldcs(px + (size_t)(g + 3) * (HD / 4));
                a0 += v0.x + v1.x + v2.x + v3.x;
                a1 += v0.y + v1.y + v2.y + v3.y;
                a2 += v0.z + v1.z + v2.z + v3.z;
                a3 += v0.w + v1.w + v2.w + v3.w;
            }
            atomicAdd(&ssum[seg_lo * D_DIM + dbase + 0], a0);
            atomicAdd(&ssum[seg_lo * D_DIM + dbase + 1], a1);
            atomicAdd(&ssum[seg_lo * D_DIM + dbase + 2], a2);
            atomicAdd(&ssum[seg_lo * D_DIM + dbase + 3], a3);
            if (tid == 0) touched[seg_lo] = 1;
        } else {
            // SLOW PATH (boundary blocks, <= 7 of 2048): per-token seg walk.
            float a0 = 0.f, a1 = 0.f, a2 = 0.f, a3 = 0.f;
            int curseg = -1;
            for (int tt = 0; tt < TOKS; tt++) {
                const int t = t0 + tt;
                const int seg = SEGOF(t);
                if (seg != curseg) {    // block-uniform branch
                    if (curseg >= 0) {
                        atomicAdd(&ssum[curseg * D_DIM + dbase + 0], a0);
                        atomicAdd(&ssum[curseg * D_DIM + dbase + 1], a1);
                        atomicAdd(&ssum[curseg * D_DIM + dbase + 2], a2);
                        atomicAdd(&ssum[curseg * D_DIM + dbase + 3], a3);
                        touched[curseg] = 1;
                    }
                    curseg = seg;
                    a0 = a1 = a2 = a3 = 0.f;
                }
                float4 v = __ldcs(&x[(size_t)t * (HD / 4) + tid]);
                a0 += v.x; a1 += v.y; a2 += v.z; a3 += v.w;
            }
            if (curseg >= 0) {
                atomicAdd(&ssum[curseg * D_DIM + dbase + 0], a0);
                atomicAdd(&ssum[curseg * D_DIM + dbase + 1], a1);
                atomicAdd(&ssum[curseg * D_DIM + dbase + 2], a2);
                atomicAdd(&ssum[curseg * D_DIM + dbase + 3], a3);
                touched[curseg] = 1;
            }
        }
        #undef SEGOF
        __syncthreads();

        for (int s = 0; s < B_SEG; s++) {
            if (touched[s]) {
                for (int i = tid; i < D_DIM; i += TPB)
                    atomicAdd(&g_sums[s * D_DIM + i], ssum[s * D_DIM + i]);
            }
        }
    }

    // ======================= Barrier / early exit ==========================
    if (bid >= NB_MLP) {
        // Arrive at ALL barriers, then leave. Never spins -> no deadlock,
        // SMs drain immediately so later waves launch.
        __threadfence();
        __syncthreads();
        if (tid == 0) {
            atomicAdd(&g_bar[0], 1u);
            atomicAdd(&g_bar[1], 1u);
            atomicAdd(&g_bar[2], 1u);
            atomicAdd(&g_bar[3], 1u);
            atomicAdd(&g_bar[4], 1u);
        }
        return;
    }

    bar_arrive(0);
    bar_wait(0);

    const int gt = bid * TPB + tid;     // 0..4095 over the 16 MLP blocks

    // ===== L1: pooled(8x128) -> h1(8x1024), silu ===========================
    {
        float* s_pool = sm;             // [8][128]
        __syncthreads();
        for (int i = tid; i < B_SEG * D_DIM; i += TPB) {
            const int b = i >> 7;
            const int cnt = cu[b + 1] - cu[b];
            const float c = (float)(cnt > 1 ? cnt : 1);
            s_pool[i] = g_sums[i] * (1.0f / (8.0f * c));
        }
        __syncthreads();

        const int j  = gt & 1023;
        const int b0 = (gt >> 10) << 1;     // 0,2,4,6
        const float* p0 = &s_pool[b0 * 128];
        const float* p1 = &s_pool[b0 * 128 + 128];
        float acc0 = b1[j], acc1 = b1[j];
        #pragma unroll 8
        for (int k = 0; k < 128; k++) {
            const float w = w1[k * 1024 + j];
            acc0 += p0[k] * w;
            acc1 += p1[k] * w;
        }
        g_h1[(b0 + 0) * 1024 + j] = silu_f(acc0);
        g_h1[(b0 + 1) * 1024 + j] = silu_f(acc1);
    }
    bar_arrive(1);
    bar_wait(1);

    // ===== L2: h1(8x1024) -> partials(16 x 8 x 256) ========================
    {
        float* s_in = sm;               // [8][64]
        __syncthreads();
        for (int i = tid; i < B_SEG * 64; i += TPB) {
            const int b = i >> 6;
            const int k = i & 63;
            s_in[i] = g_h1[b * 1024 + bid * 64 + k];
        }
        __syncthreads();

        const int j = tid;
        float acc[B_SEG];
        #pragma unroll
        for (int b = 0; b < B_SEG; b++) acc[b] = 0.0f;
        #pragma unroll 4
        for (int k = 0; k < 64; k++) {
            const float w = w2[(bid * 64 + k) * 256 + j];
            #pragma unroll
            for (int b = 0; b < B_SEG; b++)
                acc[b] += s_in[b * 64 + k] * w;
        }
        #pragma unroll
        for (int b = 0; b < B_SEG; b++)
            g_p2[(bid * B_SEG + b) * 256 + j] = acc[b];
    }
    bar_arrive(2);
    bar_wait(2);

    // ===== L3: h2(8x256) -> h3(8x512), silu ================================
    {
        float* s_h2 = sm;               // [256]
        const int b = bid >> 1;
        __syncthreads();
        {
            const int k = tid;
            float v = b2[k];
            #pragma unroll
            for (int c = 0; c < NB_MLP; c++)
                v += g_p2[(c * B_SEG + b) * 256 + k];
            s_h2[k] = v;
        }
        __syncthreads();

        const int j = ((bid & 1) << 8) + tid;
        float acc = b3[j];
        #pragma unroll 8
        for (int k = 0; k < 256; k++)
            acc += s_h2[k] * w3[k * 512 + j];
        g_h3[b * 512 + j] = silu_f(acc);
    }
    bar_arrive(3);
    bar_wait(3);

    // ===== L4: h3(8x512) -> partials(16 x 8 x 128), silu deferred ==========
    {
        float* s_in = sm;               // [8][32]
        __syncthreads();
        for (int i = tid; i < B_SEG * 32; i += TPB) {
            const int b = i >> 5;
            const int k = i & 31;
            s_in[i] = g_h3[b * 512 + bid * 32 + k];
        }
        __syncthreads();

        const int j  = tid & 127;
        const int bh = tid >> 7;        // 0 or 1
        float acc[4];
        #pragma unroll
        for (int i = 0; i < 4; i++) acc[i] = 0.0f;
        #pragma unroll 4
        for (int k = 0; k < 32; k++) {
            const float w = w4[(bid * 32 + k) * 128 + j];
            #pragma unroll
            for (int i = 0; i < 4; i++)
                acc[i] += s_in[(bh * 4 + i) * 32 + k] * w;
        }
        #pragma unroll
        for (int i = 0; i < 4; i++)
            g_p4[(bid * B_SEG + bh * 4 + i) * 128 + j] = acc[i];
    }
    bar_arrive(4);                      // blocks 1..15 arrive and exit
    if (bid != 0) return;
    bar_wait(4);                        // ONLY block 0 ever waits here

    // ===== L5 (block 0): logits + hard routing =============================
    {
        float* sred0 = sm;              // [8][128]
        float* sred1 = sm + 1024;       // [8][128]
        const int k  = tid & 127;
        const int bh = tid >> 7;        // batches {bh, bh+2, bh+4, bh+6}
        const float wa = w5[k * 2 + 0];
        const float wb = w5[k * 2 + 1];
        const float bias4 = b4[k];

        __syncthreads();
        #pragma unroll
        for (int i = 0; i < 4; i++) {
            const int b = bh + 2 * i;
            float v = bias4;
            #pragma unroll
            for (int c = 0; c < NB_MLP; c++)
                v += g_p4[(c * B_SEG + b) * 128 + k];
            const float s = silu_f(v);
            sred0[b * 128 + k] = s * wa;
            sred1[b * 128 + k] = s * wb;
        }
        __syncthreads();

        for (int off = 64; off >= 1; off >>= 1) {
            if (k < off) {
                #pragma unroll
                for (int i = 0; i < 4; i++) {
                    const int b = bh + 2 * i;
                    sred0[b * 128 + k] += sred0[b * 128 + k + off];
                    sred1[b * 128 + k] += sred1[b * 128 + k + off];
                }
            }
            __syncthreads();
        }

        if (k == 0) {
            const float bz0 = b5[0], bz1 = b5[1];
            #pragma unroll
            for (int i = 0; i < 4; i++) {
                const int b = bh + 2 * i;
                const float l0 = sred0[b * 128] + bz0;
                const float l1 = sred1[b * 128] + bz1;
                const float z  = (l1 > l0) ? 1.0f : 0.0f;
                #pragma unroll
                for (int h = 0; h < H_HEAD; h++)
                    out[b * H_HEAD + h] = z;
            }
        }
    }

    // ===== Restore entry invariants for the next call ======================
    // Safe: every block has arrived at every barrier (bar4 hit NBLK), and
    // only block 0 ever spins on bar4 — nobody else reads g_bar or g_sums.
    __syncthreads();
    for (int i = tid; i < B_SEG * D_DIM; i += TPB) g_sums[i] = 0.0f;
    if (tid < 5) g_bar[tid] = 0u;
}

// ---------------------------------------------------------------------------
// Launch: ONE graph node
// ---------------------------------------------------------------------------
extern "C" void kernel_launch(void* const* d_in, const int* in_sizes, int n_in,
                              void* d_out, int out_size)
{
    const float* x  = (const float*)d_in[0];
    const int*   cu = (const int*)  d_in[1];
    const float* w1 = (const float*)d_in[2];
    const float* b1 = (const float*)d_in[3];
    const float* w2 = (const float*)d_in[4];
    const float* b2 = (const float*)d_in[5];
    const float* w3 = (const float*)d_in[6];
    const float* b3 = (const float*)d_in[7];
    const float* w4 = (const float*)d_in[8];
    const float* b4 = (const float*)d_in[9];
    const float* w5 = (const float*)d_in[10];
    const float* b5 = (const float*)d_in[11];
    float* out = (float*)d_out;

    fused_all_kernel<<<NBLK, TPB>>>((const float4*)x, cu,
                                    w1, b1, w2, b2, w3, b3, w4, b4, w5, b5, out);
}

// round 8
// speedup vs baseline: 1.5807x; 1.2735x over previous
#include <cuda_runtime.h>
#include <cuda_bf16.h>

// Problem constants
#define T_TOK   32768
#define B_SEG   8
#define H_HEAD  8
#define D_DIM   128
#define HD      (H_HEAD * D_DIM)   // 1024 floats per token row

// Segsum geometry
#define SBLK    2048
#define STPB    256
#define TOKS    (T_TOK / SBLK)     // 16 tokens per block

// MLP geometry
#define MBLK    32
#define MTPB    256

// Scratch (device globals; g_sums and g_bar2 restored to zero by the MLP
// kernel's block 0 at the end of every call -> entry invariant holds on
// every graph replay).
__device__ float    g_sums[B_SEG * D_DIM];
__device__ float    g_h1[B_SEG * 1024];
__device__ float    g_h2[B_SEG * 256];
__device__ float    g_h3[B_SEG * 512];
__device__ float    g_h4[B_SEG * 128];
__device__ unsigned g_bar2[4];

__device__ __forceinline__ float silu_f(float x) {
    return x / (1.0f + __expf(-x));
}

// ===========================================================================
// Kernel 1: segment + head sum.  g_sums[b][d] = sum_{t in seg b} sum_h x[t,h,d]
// 2048 blocks x 256 threads, 16 token rows per block. No barriers.
// ===========================================================================
__global__ __launch_bounds__(STPB) void segsum_kernel(
    const float4* __restrict__ x, const int* __restrict__ cu)
{
    __shared__ float ssum[B_SEG * D_DIM];
    __shared__ int   touched[B_SEG];

    const int tid = threadIdx.x;
    const int bid = blockIdx.x;

    for (int i = tid; i < B_SEG * D_DIM; i += STPB) ssum[i] = 0.0f;
    if (tid < B_SEG) touched[tid] = 0;
    __syncthreads();

    const int c1 = cu[1], c2 = cu[2], c3 = cu[3], c4 = cu[4];
    const int c5 = cu[5], c6 = cu[6], c7 = cu[7];

    const int t0    = bid * TOKS;
    const int dbase = (4 * tid) & (D_DIM - 1);

    // seg = #inner boundaries <= t  (searchsorted 'right' - 1 semantics,
    // incl. duplicate boundaries / empty segments)
    #define SEGOF(t) ((int)(((t) >= c1) + ((t) >= c2) + ((t) >= c3) + \
                            ((t) >= c4) + ((t) >= c5) + ((t) >= c6) + \
                            ((t) >= c7)))

    const int seg_lo = SEGOF(t0);
    const int seg_hi = SEGOF(t0 + TOKS - 1);

    if (seg_lo == seg_hi) {
        // FAST PATH: no boundary in block. 8 independent loads per batch;
        // no other phases in this kernel, so registers are free for MLP=8.
        const float4* px = x + (size_t)t0 * (HD / 4) + tid;
        float a0 = 0.f, a1 = 0.f, a2 = 0.f, a3 = 0.f;
        #pragma unroll 1
        for (int g = 0; g < TOKS; g += 8) {
            float4 v0 = __ldcs(px + (size_t)(g + 0) * (HD / 4));
            float4 v1 = __ldcs(px + (size_t)(g + 1) * (HD / 4));
            float4 v2 = __ldcs(px + (size_t)(g + 2) * (HD / 4));
            float4 v3 = __ldcs(px + (size_t)(g + 3) * (HD / 4));
            float4 v4 = __ldcs(px + (size_t)(g + 4) * (HD / 4));
            float4 v5 = __ldcs(px + (size_t)(g + 5) * (HD / 4));
            float4 v6 = __ldcs(px + (size_t)(g + 6) * (HD / 4));
            float4 v7 = __ldcs(px + (size_t)(g + 7) * (HD / 4));
            a0 += ((v0.x + v1.x) + (v2.x + v3.x)) + ((v4.x + v5.x) + (v6.x + v7.x));
            a1 += ((v0.y + v1.y) + (v2.y + v3.y)) + ((v4.y + v5.y) + (v6.y + v7.y));
            a2 += ((v0.z + v1.z) + (v2.z + v3.z)) + ((v4.z + v5.z) + (v6.z + v7.z));
            a3 += ((v0.w + v1.w) + (v2.w + v3.w)) + ((v4.w + v5.w) + (v6.w + v7.w));
        }
        atomicAdd(&ssum[seg_lo * D_DIM + dbase + 0], a0);
        atomicAdd(&ssum[seg_lo * D_DIM + dbase + 1], a1);
        atomicAdd(&ssum[seg_lo * D_DIM + dbase + 2], a2);
        atomicAdd(&ssum[seg_lo * D_DIM + dbase + 3], a3);
        if (tid == 0) touched[seg_lo] = 1;
    } else {
        // SLOW PATH (<= 7 of 2048 blocks): per-token segment walk.
        float a0 = 0.f, a1 = 0.f, a2 = 0.f, a3 = 0.f;
        int curseg = -1;
        for (int tt = 0; tt < TOKS; tt++) {
            const int t = t0 + tt;
            const int seg = SEGOF(t);
            if (seg != curseg) {        // block-uniform branch
                if (curseg >= 0) {
                    atomicAdd(&ssum[curseg * D_DIM + dbase + 0], a0);
                    atomicAdd(&ssum[curseg * D_DIM + dbase + 1], a1);
                    atomicAdd(&ssum[curseg * D_DIM + dbase + 2], a2);
                    atomicAdd(&ssum[curseg * D_DIM + dbase + 3], a3);
                    touched[curseg] = 1;
                }
                curseg = seg;
                a0 = a1 = a2 = a3 = 0.f;
            }
            float4 v = __ldcs(&x[(size_t)t * (HD / 4) + tid]);
            a0 += v.x; a1 += v.y; a2 += v.z; a3 += v.w;
        }
        if (curseg >= 0) {
            atomicAdd(&ssum[curseg * D_DIM + dbase + 0], a0);
            atomicAdd(&ssum[curseg * D_DIM + dbase + 1], a1);
            atomicAdd(&ssum[curseg * D_DIM + dbase + 2], a2);
            atomicAdd(&ssum[curseg * D_DIM + dbase + 3], a3);
            touched[curseg] = 1;
        }
    }
    #undef SEGOF
    __syncthreads();

    for (int s = 0; s < B_SEG; s++) {
        if (touched[s]) {
            for (int i = tid; i < D_DIM; i += STPB)
                atomicAdd(&g_sums[s * D_DIM + i], ssum[s * D_DIM + i]);
        }
    }
}

// ===========================================================================
// Kernel 2: MLP with ALL weights in shared memory (immune to L2 eviction).
// 32 blocks x 256 threads. Block mb owns weight column-slices:
//   w1 cols [mb*32, +32)   -> sw1 [128][32]   16 KB
//   w2 cols [mb*8,  +8)    -> sw2 [1024][8]   32 KB
//   w3 cols [mb*16, +16)   -> sw3 [256][16]   16 KB
//   w4 cols [mb*4,  +4)    -> sw4 [512][4]     8 KB
// Activations staged into padded smem between layers. 4 grid barriers (32).
// ===========================================================================

// float offsets into dynamic smem
#define OFF_SW1   0        // 4096
#define OFF_SW2   4096     // 8192
#define OFF_SW3   12288    // 4096
#define OFF_SW4   16384    // 2048
#define OFF_STAGE 18432    // 8256 (max use: h1 at stride 1032)
#define OFF_RED   26688    // 256
#define OFF_B1    26944    // 32
#define OFF_B2    26976    // 8
#define OFF_B3    26984    // 16
#define OFF_B4    27000    // 4
#define SMEM_FLOATS 27008
#define SMEM_MLP (SMEM_FLOATS * 4)

__device__ __forceinline__ void mbar_arrive(int i) {
    __threadfence();
    __syncthreads();
    if (threadIdx.x == 0) atomicAdd(&g_bar2[i], 1u);
}
__device__ __forceinline__ void mbar_wait(int i) {
    if (threadIdx.x == 0) {
        volatile unsigned* p = &g_bar2[i];
        while (*p < MBLK) __nanosleep(32);
    }
    __syncthreads();
    __threadfence();
}

__global__ __launch_bounds__(MTPB) void mlp_kernel(
    const int*   __restrict__ cu,
    const float* __restrict__ w1, const float* __restrict__ b1,
    const float* __restrict__ w2, const float* __restrict__ b2,
    const float* __restrict__ w3, const float* __restrict__ b3,
    const float* __restrict__ w4, const float* __restrict__ b4,
    const float* __restrict__ w5, const float* __restrict__ b5,
    float* __restrict__ out)
{
    extern __shared__ float sm[];
    float* sw1   = sm + OFF_SW1;
    float* sw2   = sm + OFF_SW2;
    float* sw3   = sm + OFF_SW3;
    float* sw4   = sm + OFF_SW4;
    float* stage = sm + OFF_STAGE;
    float* red   = sm + OFF_RED;

    const int tid = threadIdx.x;
    const int mb  = blockIdx.x;

    // ---- Bulk-load weight slices into smem (independent float4 loads) ----
    {
        float4* d1 = (float4*)sw1;  const float4* s1 = (const float4*)w1;
        float4* d2 = (float4*)sw2;  const float4* s2 = (const float4*)w2;
        float4* d3 = (float4*)sw3;  const float4* s3 = (const float4*)w3;
        float4* d4 = (float4*)sw4;  const float4* s4 = (const float4*)w4;
        #pragma unroll 1
        for (int idx = tid; idx < 1024; idx += MTPB) {   // sw1: 128 rows x 8 f4
            const int r = idx >> 3, c = idx & 7;
            d1[idx] = s1[r * 256 + mb * 8 + c];
        }
        #pragma unroll 1
        for (int idx = tid; idx < 2048; idx += MTPB) {   // sw2: 1024 rows x 2 f4
            const int r = idx >> 1, c = idx & 1;
            d2[idx] = s2[r * 64 + mb * 2 + c];
        }
        #pragma unroll 1
        for (int idx = tid; idx < 1024; idx += MTPB) {   // sw3: 256 rows x 4 f4
            const int r = idx >> 2, c = idx & 3;
            d3[idx] = s3[r * 128 + mb * 4 + c];
        }
        #pragma unroll 1
        for (int idx = tid; idx < 512; idx += MTPB) {    // sw4: 512 rows x 1 f4
            d4[idx] = s4[idx * 32 + mb];
        }
        if (tid < 32) sm[OFF_B1 + tid] = b1[mb * 32 + tid];
        if (tid < 8)  sm[OFF_B2 + tid] = b2[mb * 8 + tid];
        if (tid < 16) sm[OFF_B3 + tid] = b3[mb * 16 + tid];
        if (tid < 4)  sm[OFF_B4 + tid] = b4[mb * 4 + tid];
    }

    // ---- pooled input (uses stage[0..1023]) ----
    for (int i = tid; i < B_SEG * D_DIM; i += MTPB) {
        const int b = i >> 7;
        const int cnt = cu[b + 1] - cu[b];
        const float c = (float)(cnt > 1 ? cnt : 1);
        stage[i] = g_sums[i] * (1.0f / (8.0f * c));
    }
    __syncthreads();

    // ===== L1: pooled(8x128) -> h1(8x1024), silu. 256 outputs/block =======
    {
        const int b = tid >> 5;         // 0..7
        const int j = tid & 31;         // local col
        const float* pool = &stage[b * 128];
        float acc = sm[OFF_B1 + j];
        #pragma unroll 8
        for (int k = 0; k < 128; k++)
            acc += pool[k] * sw1[k * 32 + j];
        g_h1[b * 1024 + mb * 32 + j] = silu_f(acc);
    }
    mbar_arrive(0);
    mbar_wait(0);

    // ---- stage h1 (stride 1032 to dodge bank conflicts) ----
    for (int i = tid; i < 8192; i += MTPB)
        stage[(i >> 10) * 1032 + (i & 1023)] = g_h1[i];
    __syncthreads();

    // ===== L2: h1 -> h2(8x256), no act. 64 outputs, 4-way k-split ========
    {
        const int oidx = tid & 63;      // b*8 + j
        const int b = oidx >> 3, j = oidx & 7;
        const int kc = tid >> 6;        // 0..3
        const float* hin = &stage[b * 1032 + kc * 256];
        const float* wv  = &sw2[kc * 256 * 8 + j];
        float acc = 0.f;
        #pragma unroll 8
        for (int k = 0; k < 256; k++)
            acc += hin[k] * wv[k * 8];
        red[tid] = acc;
        __syncthreads();
        if (tid < 64) {
            float v = red[tid] + red[tid + 64] + red[tid + 128] + red[tid + 192]
                    + sm[OFF_B2 + j];
            g_h2[b * 256 + mb * 8 + j] = v;
        }
    }
    mbar_arrive(1);
    mbar_wait(1);

    // ---- stage h2 (stride 264) ----
    for (int i = tid; i < 2048; i += MTPB)
        stage[(i >> 8) * 264 + (i & 255)] = g_h2[i];
    __syncthreads();

    // ===== L3: h2 -> h3(8x512), silu. 128 outputs, 2-way k-split =========
    {
        const int oidx = tid & 127;
        const int b = oidx >> 4, j = oidx & 15;
        const int kc = tid >> 7;        // 0..1
        const float* hin = &stage[b * 264 + kc * 128];
        const float* wv  = &sw3[kc * 128 * 16 + j];
        float acc = 0.f;
        #pragma unroll 8
        for (int k = 0; k < 128; k++)
            acc += hin[k] * wv[k * 16];
        red[tid] = acc;
        __syncthreads();
        if (tid < 128) {
            float v = red[tid] + red[tid + 128] + sm[OFF_B3 + j];
            g_h3[b * 512 + mb * 16 + j] = silu_f(v);
        }
    }
    mbar_arrive(2);
    mbar_wait(2);

    // ---- stage h3 (stride 516) ----
    for (int i = tid; i < 4096; i += MTPB)
        stage[(i >> 9) * 516 + (i & 511)] = g_h3[i];
    __syncthreads();

    // ===== L4: h3 -> h4(8x128), bias added, silu deferred. 32 outs, 8-split
    {
        const int oidx = tid & 31;
        const int b = oidx >> 2, j = oidx & 3;
        const int kc = tid >> 5;        // 0..7
        const float* hin = &stage[b * 516 + kc * 64];
        const float* wv  = &sw4[kc * 64 * 4 + j];
        float acc = 0.f;
        #pragma unroll 8
        for (int k = 0; k < 64; k++)
            acc += hin[k] * wv[k * 4];
        red[tid] = acc;
        __syncthreads();
        if (tid < 32) {
            float v = sm[OFF_B4 + j];
            #pragma unroll
            for (int c = 0; c < 8; c++) v += red[tid + c * 32];
            g_h4[b * 128 + mb * 4 + j] = v;
        }
    }
    mbar_arrive(3);                     // blocks 1..31 arrive and exit
    if (mb != 0) return;
    mbar_wait(3);                       // only block 0 ever waits here

    // ===== L5 (block 0): logits + hard routing =============================
    {
        float* sred0 = stage;           // [8][128]
        float* sred1 = stage + 1024;    // [8][128]
        const int k  = tid & 127;
        const int bh = tid >> 7;        // batches {bh, bh+2, bh+4, bh+6}
        const float wa = w5[k * 2 + 0];
        const float wb = w5[k * 2 + 1];

        __syncthreads();
        #pragma unroll
        for (int i = 0; i < 4; i++) {
            const int b = bh + 2 * i;
            const float s = silu_f(g_h4[b * 128 + k]);
            sred0[b * 128 + k] = s * wa;
            sred1[b * 128 + k] = s * wb;
        }
        __syncthreads();

        for (int off = 64; off >= 1; off >>= 1) {
            if (k < off) {
                #pragma unroll
                for (int i = 0; i < 4; i++) {
                    const int b = bh + 2 * i;
                    sred0[b * 128 + k] += sred0[b * 128 + k + off];
                    sred1[b * 128 + k] += sred1[b * 128 + k + off];
                }
            }
            __syncthreads();
        }

        if (k == 0) {
            const float bz0 = b5[0], bz1 = b5[1];
            #pragma unroll
            for (int i = 0; i < 4; i++) {
                const int b = bh + 2 * i;
                const float l0 = sred0[b * 128] + bz0;
                const float l1 = sred1[b * 128] + bz1;
                const float z  = (l1 > l0) ? 1.0f : 0.0f;
                #pragma unroll
                for (int h = 0; h < H_HEAD; h++)
                    out[b * H_HEAD + h] = z;
            }
        }
    }

    // ---- restore entry invariants (block 0 only; all others have exited
    //      past their last access of g_sums / g_bar2) ----
    __syncthreads();
    for (int i = tid; i < B_SEG * D_DIM; i += MTPB) g_sums[i] = 0.0f;
    if (tid < 4) g_bar2[tid] = 0u;
}

// ---------------------------------------------------------------------------
// Launch: 2 graph nodes
// ---------------------------------------------------------------------------
extern "C" void kernel_launch(void* const* d_in, const int* in_sizes, int n_in,
                              void* d_out, int out_size)
{
    const float* x  = (const float*)d_in[0];
    const int*   cu = (const int*)  d_in[1];
    const float* w1 = (const float*)d_in[2];
    const float* b1 = (const float*)d_in[3];
    const float* w2 = (const float*)d_in[4];
    const float* b2 = (const float*)d_in[5];
    const float* w3 = (const float*)d_in[6];
    const float* b3 = (const float*)d_in[7];
    const float* w4 = (const float*)d_in[8];
    const float* b4 = (const float*)d_in[9];
    const float* w5 = (const float*)d_in[10];
    const float* b5 = (const float*)d_in[11];
    float* out = (float*)d_out;

    static bool attr_done = false;
    if (!attr_done) {
        cudaFuncSetAttribute(mlp_kernel,
                             cudaFuncAttributeMaxDynamicSharedMemorySize,
                             SMEM_MLP);
        attr_done = true;
    }

    segsum_kernel<<<SBLK, STPB>>>((const float4*)x, cu);
    mlp_kernel<<<MBLK, MTPB, SMEM_MLP>>>(cu, w1, b1, w2, b2, w3, b3,
                                         w4, b4, w5, b5, out);
}

// round 9
// speedup vs baseline: 1.7704x; 1.1200x over previous
#include <cuda_runtime.h>
#include <cuda_bf16.h>

// Problem constants
#define T_TOK   32768
#define B_SEG   8
#define H_HEAD  8
#define D_DIM   128
#define HD      (H_HEAD * D_DIM)   // 1024 floats per token row

// Segsum geometry
#define SBLK    2048
#define STPB    256
#define TOKS    (T_TOK / SBLK)     // 16 tokens per block

// MLP geometry
#define MBLK    16
#define MTPB    256

// Scratch (device globals; g_sums and g_bar2 restored to zero by the MLP
// kernel's block 0 at the end of every call -> entry invariant holds on
// every graph replay).
__device__ float    g_sums[B_SEG * D_DIM];
__device__ float    g_h1[B_SEG * 1024];
__device__ float    g_h2[B_SEG * 256];
__device__ float    g_h3[B_SEG * 512];
__device__ float    g_h4[B_SEG * 128];
__device__ unsigned g_bar2[4];

__device__ __forceinline__ float silu_f(float x) {
    return x / (1.0f + __expf(-x));
}

// ===========================================================================
// Kernel 1: segment + head sum.  g_sums[b][d] = sum_{t in seg b} sum_h x[t,h,d]
// 2048 blocks x 256 threads, 16 token rows per block. No barriers.
// ===========================================================================
__global__ __launch_bounds__(STPB) void segsum_kernel(
    const float4* __restrict__ x, const int* __restrict__ cu)
{
    __shared__ float ssum[B_SEG * D_DIM];
    __shared__ int   touched[B_SEG];

    const int tid = threadIdx.x;
    const int bid = blockIdx.x;

    for (int i = tid; i < B_SEG * D_DIM; i += STPB) ssum[i] = 0.0f;
    if (tid < B_SEG) touched[tid] = 0;
    __syncthreads();

    const int c1 = cu[1], c2 = cu[2], c3 = cu[3], c4 = cu[4];
    const int c5 = cu[5], c6 = cu[6], c7 = cu[7];

    const int t0    = bid * TOKS;
    const int dbase = (4 * tid) & (D_DIM - 1);

    // seg = #inner boundaries <= t  (searchsorted 'right' - 1 semantics,
    // incl. duplicate boundaries / empty segments)
    #define SEGOF(t) ((int)(((t) >= c1) + ((t) >= c2) + ((t) >= c3) + \
                            ((t) >= c4) + ((t) >= c5) + ((t) >= c6) + \
                            ((t) >= c7)))

    const int seg_lo = SEGOF(t0);
    const int seg_hi = SEGOF(t0 + TOKS - 1);

    if (seg_lo == seg_hi) {
        // FAST PATH: no boundary in block; 8 independent loads per batch.
        const float4* px = x + (size_t)t0 * (HD / 4) + tid;
        float a0 = 0.f, a1 = 0.f, a2 = 0.f, a3 = 0.f;
        #pragma unroll 1
        for (int g = 0; g < TOKS; g += 8) {
            float4 v0 = __ldcs(px + (size_t)(g + 0) * (HD / 4));
            float4 v1 = __ldcs(px + (size_t)(g + 1) * (HD / 4));
            float4 v2 = __ldcs(px + (size_t)(g + 2) * (HD / 4));
            float4 v3 = __ldcs(px + (size_t)(g + 3) * (HD / 4));
            float4 v4 = __ldcs(px + (size_t)(g + 4) * (HD / 4));
            float4 v5 = __ldcs(px + (size_t)(g + 5) * (HD / 4));
            float4 v6 = __ldcs(px + (size_t)(g + 6) * (HD / 4));
            float4 v7 = __ldcs(px + (size_t)(g + 7) * (HD / 4));
            a0 += ((v0.x + v1.x) + (v2.x + v3.x)) + ((v4.x + v5.x) + (v6.x + v7.x));
            a1 += ((v0.y + v1.y) + (v2.y + v3.y)) + ((v4.y + v5.y) + (v6.y + v7.y));
            a2 += ((v0.z + v1.z) + (v2.z + v3.z)) + ((v4.z + v5.z) + (v6.z + v7.z));
            a3 += ((v0.w + v1.w) + (v2.w + v3.w)) + ((v4.w + v5.w) + (v6.w + v7.w));
        }
        atomicAdd(&ssum[seg_lo * D_DIM + dbase + 0], a0);
        atomicAdd(&ssum[seg_lo * D_DIM + dbase + 1], a1);
        atomicAdd(&ssum[seg_lo * D_DIM + dbase + 2], a2);
        atomicAdd(&ssum[seg_lo * D_DIM + dbase + 3], a3);
        if (tid == 0) touched[seg_lo] = 1;
    } else {
        // SLOW PATH (<= 7 of 2048 blocks): per-token segment walk.
        float a0 = 0.f, a1 = 0.f, a2 = 0.f, a3 = 0.f;
        int curseg = -1;
        for (int tt = 0; tt < TOKS; tt++) {
            const int t = t0 + tt;
            const int seg = SEGOF(t);
            if (seg != curseg) {
                if (curseg >= 0) {
                    atomicAdd(&ssum[curseg * D_DIM + dbase + 0], a0);
                    atomicAdd(&ssum[curseg * D_DIM + dbase + 1], a1);
                    atomicAdd(&ssum[curseg * D_DIM + dbase + 2], a2);
                    atomicAdd(&ssum[curseg * D_DIM + dbase + 3], a3);
                    touched[curseg] = 1;
                }
                curseg = seg;
                a0 = a1 = a2 = a3 = 0.f;
            }
            float4 v = __ldcs(&x[(size_t)t * (HD / 4) + tid]);
            a0 += v.x; a1 += v.y; a2 += v.z; a3 += v.w;
        }
        if (curseg >= 0) {
            atomicAdd(&ssum[curseg * D_DIM + dbase + 0], a0);
            atomicAdd(&ssum[curseg * D_DIM + dbase + 1], a1);
            atomicAdd(&ssum[curseg * D_DIM + dbase + 2], a2);
            atomicAdd(&ssum[curseg * D_DIM + dbase + 3], a3);
            touched[curseg] = 1;
        }
    }
    #undef SEGOF
    __syncthreads();

    for (int s = 0; s < B_SEG; s++) {
        if (touched[s]) {
            for (int i = tid; i < D_DIM; i += STPB)
                atomicAdd(&g_sums[s * D_DIM + i], ssum[s * D_DIM + i]);
        }
    }
}

// ===========================================================================
// Kernel 2: MLP, 16 blocks x 256 threads. All weights cp.async'd into smem
// (fire-and-forget LDGSTS: whole 2.4 MB in flight at once -> DRAM-BW fetch,
// no LDG->STS serialization). Activations staged via float4 into padded smem.
// Block mb owns columns: w1[.,mb*64+64) w2[.,mb*16+16) w3[.,mb*32+32)
// w4[.,mb*8+8).
// ===========================================================================

// float offsets into dynamic smem (all 16B-aligned)
#define OFF_SW1   0        //  8192 floats (128 x 64)
#define OFF_SW2   8192     // 16384 floats (1024 x 16)
#define OFF_SW3   24576    //  8192 floats (256 x 32)
#define OFF_SW4   32768    //  4096 floats (512 x 8)
#define OFF_STAGE 36864    //  8256 floats (h1 at stride 1032 max)
#define OFF_RED   45120    //   256
#define OFF_B1    45376    //    64
#define OFF_B2    45440    //    16
#define OFF_B3    45456    //    32
#define OFF_B4    45488    //     8
#define SMEM_FLOATS 45504
#define SMEM_MLP (SMEM_FLOATS * 4)   // 182016 bytes

#define CP_ASYNC16(smem_u32, gptr) \
    asm volatile("cp.async.cg.shared.global [%0], [%1], 16;" \
                 :: "r"(smem_u32), "l"(gptr) : "memory")

__device__ __forceinline__ void mbar_arrive(int i) {
    __threadfence();
    __syncthreads();
    if (threadIdx.x == 0) atomicAdd(&g_bar2[i], 1u);
}
__device__ __forceinline__ void mbar_wait(int i) {
    if (threadIdx.x == 0) {
        volatile unsigned* p = &g_bar2[i];
        while (*p < MBLK) __nanosleep(32);
    }
    __syncthreads();
    __threadfence();
}

__global__ __launch_bounds__(MTPB) void mlp_kernel(
    const int*   __restrict__ cu,
    const float* __restrict__ w1, const float* __restrict__ b1,
    const float* __restrict__ w2, const float* __restrict__ b2,
    const float* __restrict__ w3, const float* __restrict__ b3,
    const float* __restrict__ w4, const float* __restrict__ b4,
    const float* __restrict__ w5, const float* __restrict__ b5,
    float* __restrict__ out)
{
    extern __shared__ float sm[];
    float* sw1   = sm + OFF_SW1;
    float* sw2   = sm + OFF_SW2;
    float* sw3   = sm + OFF_SW3;
    float* sw4   = sm + OFF_SW4;
    float* stage = sm + OFF_STAGE;
    float* red   = sm + OFF_RED;

    const int tid = threadIdx.x;
    const int mb  = blockIdx.x;

    // ---- Fire-and-forget weight preload: 36 cp.asyncs per thread ----------
    {
        const unsigned s1 = (unsigned)__cvta_generic_to_shared(sw1);
        const unsigned s2 = (unsigned)__cvta_generic_to_shared(sw2);
        const unsigned s3 = (unsigned)__cvta_generic_to_shared(sw3);
        const unsigned s4 = (unsigned)__cvta_generic_to_shared(sw4);

        // sw1: 128 rows x 16 f4/row  (2048 f4, 8/thread)
        #pragma unroll
        for (int n = 0; n < 8; n++) {
            const int idx = tid + n * MTPB;
            const int r = idx >> 4, c = idx & 15;
            CP_ASYNC16(s1 + idx * 16, w1 + r * 1024 + mb * 64 + c * 4);
        }
        // sw2: 1024 rows x 4 f4/row  (4096 f4, 16/thread)
        #pragma unroll
        for (int n = 0; n < 16; n++) {
            const int idx = tid + n * MTPB;
            const int r = idx >> 2, c = idx & 3;
            CP_ASYNC16(s2 + idx * 16, w2 + r * 256 + mb * 16 + c * 4);
        }
        // sw3: 256 rows x 8 f4/row   (2048 f4, 8/thread)
        #pragma unroll
        for (int n = 0; n < 8; n++) {
            const int idx = tid + n * MTPB;
            const int r = idx >> 3, c = idx & 7;
            CP_ASYNC16(s3 + idx * 16, w3 + r * 512 + mb * 32 + c * 4);
        }
        // sw4: 512 rows x 2 f4/row   (1024 f4, 4/thread)
        #pragma unroll
        for (int n = 0; n < 4; n++) {
            const int idx = tid + n * MTPB;
            const int r = idx >> 1, c = idx & 1;
            CP_ASYNC16(s4 + idx * 16, w4 + r * 128 + mb * 8 + c * 4);
        }
        asm volatile("cp.async.commit_group;" ::: "memory");
    }

    // ---- biases (tiny, plain loads; independent of cp.async group) --------
    if (tid < 64) sm[OFF_B1 + tid] = b1[mb * 64 + tid];
    if (tid < 16) sm[OFF_B2 + tid] = b2[mb * 16 + tid];
    if (tid < 32) sm[OFF_B3 + tid] = b3[mb * 32 + tid];
    if (tid < 8)  sm[OFF_B4 + tid] = b4[mb * 8 + tid];

    // ---- pooled input: 1 float4 per thread + scale ------------------------
    {
        const float4 v = ((const float4*)g_sums)[tid];
        const int b = tid >> 5;                 // 32 f4 per batch row
        const int cnt = cu[b + 1] - cu[b];
        const float c = 1.0f / (8.0f * (float)(cnt > 1 ? cnt : 1));
        float4* dst = (float4*)&stage[0];
        float4 o; o.x = v.x * c; o.y = v.y * c; o.z = v.z * c; o.w = v.w * c;
        dst[tid] = o;
    }

    asm volatile("cp.async.wait_group 0;" ::: "memory");
    __syncthreads();

    // ===== L1: pooled(8x128) -> h1 slice (8 x 64 cols), silu ==============
    {
        const int j  = tid & 63;
        const int b0 = (tid >> 6) << 1;         // 0,2,4,6
        const float* p0 = &stage[b0 * 128];
        const float* p1 = &stage[b0 * 128 + 128];
        float acc0 = sm[OFF_B1 + j], acc1 = acc0;
        #pragma unroll 8
        for (int k = 0; k < 128; k++) {
            const float w = sw1[k * 64 + j];
            acc0 += p0[k] * w;
            acc1 += p1[k] * w;
        }
        g_h1[(b0 + 0) * 1024 + mb * 64 + j] = silu_f(acc0);
        g_h1[(b0 + 1) * 1024 + mb * 64 + j] = silu_f(acc1);
    }
    mbar_arrive(0);
    mbar_wait(0);

    // ---- stage h1 (float4 loads, padded stride 1032) ----------------------
    {
        const float4* src = (const float4*)g_h1;
        #pragma unroll
        for (int n = 0; n < 8; n++) {
            const int idx = tid + n * MTPB;     // 2048 f4
            const float4 v = src[idx];
            const int base = idx << 2;
            *(float4*)&stage[(base >> 10) * 1032 + (base & 1023)] = v;
        }
    }
    __syncthreads();

    // ===== L2: h1 -> h2 slice (8 x 16 cols), no act; 2-way k-split ========
    {
        const int oidx = tid & 127;
        const int b = oidx >> 4, j = oidx & 15;
        const int kc = tid >> 7;                // 0..1
        const float* hin = &stage[b * 1032 + kc * 512];
        const float* wv  = &sw2[kc * 512 * 16 + j];
        float acc = 0.f;
        #pragma unroll 8
        for (int k = 0; k < 512; k++)
            acc += hin[k] * wv[k * 16];
        red[tid] = acc;
        __syncthreads();
        if (tid < 128) {
            g_h2[b * 256 + mb * 16 + j] =
                red[tid] + red[tid + 128] + sm[OFF_B2 + j];
        }
    }
    mbar_arrive(1);
    mbar_wait(1);

    // ---- stage h2 (stride 264) --------------------------------------------
    {
        const float4* src = (const float4*)g_h2;
        #pragma unroll
        for (int n = 0; n < 2; n++) {
            const int idx = tid + n * MTPB;     // 512 f4
            const float4 v = src[idx];
            const int base = idx << 2;
            *(float4*)&stage[(base >> 8) * 264 + (base & 255)] = v;
        }
    }
    __syncthreads();

    // ===== L3: h2 -> h3 slice (8 x 32 cols), silu =========================
    {
        const int b = tid >> 5, j = tid & 31;
        const float* hin = &stage[b * 264];
        float acc = sm[OFF_B3 + j];
        #pragma unroll 8
        for (int k = 0; k < 256; k++)
            acc += hin[k] * sw3[k * 32 + j];
        g_h3[b * 512 + mb * 32 + j] = silu_f(acc);
    }
    mbar_arrive(2);
    mbar_wait(2);

    // ---- stage h3 (stride 516) --------------------------------------------
    {
        const float4* src = (const float4*)g_h3;
        #pragma unroll
        for (int n = 0; n < 4; n++) {
            const int idx = tid + n * MTPB;     // 1024 f4
            const float4 v = src[idx];
            const int base = idx << 2;
            *(float4*)&stage[(base >> 9) * 516 + (base & 511)] = v;
        }
    }
    __syncthreads();

    // ===== L4: h3 -> h4 slice (8 x 8 cols), silu deferred; 4-way split ====
    {
        const int oidx = tid & 63;
        const int b = oidx >> 3, j = oidx & 7;
        const int kc = tid >> 6;                // 0..3
        const float* hin = &stage[b * 516 + kc * 128];
        const float* wv  = &sw4[kc * 128 * 8 + j];
        float acc = 0.f;
        #pragma unroll 8
        for (int k = 0; k < 128; k++)
            acc += hin[k] * wv[k * 8];
        red[tid] = acc;
        __syncthreads();
        if (tid < 64) {
            g_h4[b * 128 + mb * 8 + j] =
                red[tid] + red[tid + 64] + red[tid + 128] + red[tid + 192]
                + sm[OFF_B4 + j];
        }
    }
    mbar_arrive(3);                             // blocks 1..15 arrive and exit
    if (mb != 0) return;
    mbar_wait(3);                               // only block 0 ever waits here

    // ===== L5 (block 0): logits + hard routing =============================
    {
        float* sred0 = stage;                   // [8][128]
        float* sred1 = stage + 1024;            // [8][128]
        const int k  = tid & 127;
        const int bh = tid >> 7;                // batches {bh, bh+2, bh+4, bh+6}
        const float wa = w5[k * 2 + 0];
        const float wb = w5[k * 2 + 1];

        __syncthreads();
        #pragma unroll
        for (int i = 0; i < 4; i++) {
            const int b = bh + 2 * i;
            const float s = silu_f(g_h4[b * 128 + k]);
            sred0[b * 128 + k] = s * wa;
            sred1[b * 128 + k] = s * wb;
        }
        __syncthreads();

        for (int off = 64; off >= 1; off >>= 1) {
            if (k < off) {
                #pragma unroll
                for (int i = 0; i < 4; i++) {
                    const int b = bh + 2 * i;
                    sred0[b * 128 + k] += sred0[b * 128 + k + off];
                    sred1[b * 128 + k] += sred1[b * 128 + k + off];
                }
            }
            __syncthreads();
        }

        if (k == 0) {
            const float bz0 = b5[0], bz1 = b5[1];
            #pragma unroll
            for (int i = 0; i < 4; i++) {
                const int b = bh + 2 * i;
                const float l0 = sred0[b * 128] + bz0;
                const float l1 = sred1[b * 128] + bz1;
                const float z  = (l1 > l0) ? 1.0f : 0.0f;
                #pragma unroll
                for (int h = 0; h < H_HEAD; h++)
                    out[b * H_HEAD + h] = z;
            }
        }
    }

    // ---- restore entry invariants (block 0 only; all others exited) -------
    __syncthreads();
    for (int i = tid; i < B_SEG * D_DIM; i += MTPB) g_sums[i] = 0.0f;
    if (tid < 4) g_bar2[tid] = 0u;
}

// ---------------------------------------------------------------------------
// Launch: 2 graph nodes
// ---------------------------------------------------------------------------
extern "C" void kernel_launch(void* const* d_in, const int* in_sizes, int n_in,
                              void* d_out, int out_size)
{
    const float* x  = (const float*)d_in[0];
    const int*   cu = (const int*)  d_in[1];
    const float* w1 = (const float*)d_in[2];
    const float* b1 = (const float*)d_in[3];
    const float* w2 = (const float*)d_in[4];
    const float* b2 = (const float*)d_in[5];
    const float* w3 = (const float*)d_in[6];
    const float* b3 = (const float*)d_in[7];
    const float* w4 = (const float*)d_in[8];
    const float* b4 = (const float*)d_in[9];
    const float* w5 = (const float*)d_in[10];
    const float* b5 = (const float*)d_in[11];
    float* out = (float*)d_out;

    cudaFuncSetAttribute(mlp_kernel,
                         cudaFuncAttributeMaxDynamicSharedMemorySize,
                         SMEM_MLP);

    segsum_kernel<<<SBLK, STPB>>>((const float4*)x, cu);
    mlp_kernel<<<MBLK, MTPB, SMEM_MLP>>>(cu, w1, b1, w2, b2, w3, b3,
                                         w4, b4, w5, b5, out);
}

// round 11
// speedup vs baseline: 1.8997x; 1.0730x over previous
#include <cuda_runtime.h>
#include <cuda_bf16.h>

// Problem constants
#define T_TOK   32768
#define B_SEG   8
#define H_HEAD  8
#define D_DIM   128
#define HD      (H_HEAD * D_DIM)   // 1024 floats per token row

// Segsum geometry
#define SBLK    2048
#define STPB    256
#define TOKS    (T_TOK / SBLK)     // 16 tokens per block

// MLP geometry
#define MBLK    16
#define MTPB    256

// Scratch (device globals; g_sums and g_bar2 restored to zero by the MLP
// kernel's block 0 at the end of every call -> entry invariant holds on
// every graph replay).
__device__ float    g_sums[B_SEG * D_DIM];
__device__ float    g_h1[B_SEG * 1024];
__device__ float    g_h2[B_SEG * 256];
__device__ float    g_h3[B_SEG * 512];
__device__ float    g_h4[B_SEG * 128];
__device__ unsigned g_bar2[4];

__device__ __forceinline__ float silu_f(float x) {
    return x / (1.0f + __expf(-x));
}

// ===========================================================================
// Kernel 1: segment + head sum.  g_sums[b][d] = sum_{t in seg b} sum_h x[t,h,d]
// ===========================================================================
__global__ __launch_bounds__(STPB) void segsum_kernel(
    const float4* __restrict__ x, const int* __restrict__ cu)
{
    __shared__ float ssum[B_SEG * D_DIM];
    __shared__ int   touched[B_SEG];

    const int tid = threadIdx.x;
    const int bid = blockIdx.x;

    for (int i = tid; i < B_SEG * D_DIM; i += STPB) ssum[i] = 0.0f;
    if (tid < B_SEG) touched[tid] = 0;
    __syncthreads();

    const int c1 = cu[1], c2 = cu[2], c3 = cu[3], c4 = cu[4];
    const int c5 = cu[5], c6 = cu[6], c7 = cu[7];

    const int t0    = bid * TOKS;
    const int dbase = (4 * tid) & (D_DIM - 1);

    #define SEGOF(t) ((int)(((t) >= c1) + ((t) >= c2) + ((t) >= c3) + \
                            ((t) >= c4) + ((t) >= c5) + ((t) >= c6) + \
                            ((t) >= c7)))

    const int seg_lo = SEGOF(t0);
    const int seg_hi = SEGOF(t0 + TOKS - 1);

    if (seg_lo == seg_hi) {
        const float4* px = x + (size_t)t0 * (HD / 4) + tid;
        float a0 = 0.f, a1 = 0.f, a2 = 0.f, a3 = 0.f;
        #pragma unroll 1
        for (int g = 0; g < TOKS; g += 8) {
            float4 v0 = __ldcs(px + (size_t)(g + 0) * (HD / 4));
            float4 v1 = __ldcs(px + (size_t)(g + 1) * (HD / 4));
            float4 v2 = __ldcs(px + (size_t)(g + 2) * (HD / 4));
            float4 v3 = __ldcs(px + (size_t)(g + 3) * (HD / 4));
            float4 v4 = __ldcs(px + (size_t)(g + 4) * (HD / 4));
            float4 v5 = __ldcs(px + (size_t)(g + 5) * (HD / 4));
            float4 v6 = __ldcs(px + (size_t)(g + 6) * (HD / 4));
            float4 v7 = __ldcs(px + (size_t)(g + 7) * (HD / 4));
            a0 += ((v0.x + v1.x) + (v2.x + v3.x)) + ((v4.x + v5.x) + (v6.x + v7.x));
            a1 += ((v0.y + v1.y) + (v2.y + v3.y)) + ((v4.y + v5.y) + (v6.y + v7.y));
            a2 += ((v0.z + v1.z) + (v2.z + v3.z)) + ((v4.z + v5.z) + (v6.z + v7.z));
            a3 += ((v0.w + v1.w) + (v2.w + v3.w)) + ((v4.w + v5.w) + (v6.w + v7.w));
        }
        atomicAdd(&ssum[seg_lo * D_DIM + dbase + 0], a0);
        atomicAdd(&ssum[seg_lo * D_DIM + dbase + 1], a1);
        atomicAdd(&ssum[seg_lo * D_DIM + dbase + 2], a2);
        atomicAdd(&ssum[seg_lo * D_DIM + dbase + 3], a3);
        if (tid == 0) touched[seg_lo] = 1;
    } else {
        float a0 = 0.f, a1 = 0.f, a2 = 0.f, a3 = 0.f;
        int curseg = -1;
        for (int tt = 0; tt < TOKS; tt++) {
            const int t = t0 + tt;
            const int seg = SEGOF(t);
            if (seg != curseg) {
                if (curseg >= 0) {
                    atomicAdd(&ssum[curseg * D_DIM + dbase + 0], a0);
                    atomicAdd(&ssum[curseg * D_DIM + dbase + 1], a1);
                    atomicAdd(&ssum[curseg * D_DIM + dbase + 2], a2);
                    atomicAdd(&ssum[curseg * D_DIM + dbase + 3], a3);
                    touched[curseg] = 1;
                }
                curseg = seg;
                a0 = a1 = a2 = a3 = 0.f;
            }
            float4 v = __ldcs(&x[(size_t)t * (HD / 4) + tid]);
            a0 += v.x; a1 += v.y; a2 += v.z; a3 += v.w;
        }
        if (curseg >= 0) {
            atomicAdd(&ssum[curseg * D_DIM + dbase + 0], a0);
            atomicAdd(&ssum[curseg * D_DIM + dbase + 1], a1);
            atomicAdd(&ssum[curseg * D_DIM + dbase + 2], a2);
            atomicAdd(&ssum[curseg * D_DIM + dbase + 3], a3);
            touched[curseg] = 1;
        }
    }
    #undef SEGOF
    __syncthreads();

    for (int s = 0; s < B_SEG; s++) {
        if (touched[s]) {
            for (int i = tid; i < D_DIM; i += STPB)
                atomicAdd(&g_sums[s * D_DIM + i], ssum[s * D_DIM + i]);
        }
    }
}

// ===========================================================================
// Kernel 2: MLP, 16 blocks x 256 threads. Weights cp.async'd (4 commit
// groups -> staged waits overlap fetch with compute). Each thread computes
// 4 consecutive output cols via float4 LDS: 5 LDS.128 per 16 FFMA.
// Block mb owns cols: w1[.,mb*64+64) w2[.,mb*16+16) w3[.,mb*32+32) w4[.,mb*8+8)
// ===========================================================================

// float offsets into dynamic smem (all 16B-aligned)
#define OFF_SW1   0        //  8192 (128 x 64)
#define OFF_SW2   8192     // 16384 (1024 x 16)
#define OFF_SW3   24576    //  8192 (256 x 32)
#define OFF_SW4   32768    //  4096 (512 x 8)
#define OFF_STAGE 36864    //  8320 (h1 at stride 1028 max; L5 uses 2048)
#define OFF_RED   45184    //  1024 (256 x float4)
#define OFF_B1    46208    //    64
#define OFF_B2    46272    //    16
#define OFF_B3    46288    //    32
#define OFF_B4    46320    //     8
#define SMEM_FLOATS 46336
#define SMEM_MLP (SMEM_FLOATS * 4)   // 185344 bytes

// Padded staging strides: stride % 32 == 4 -> 8 batch rows hit distinct
// bank-quads on broadcast float4 reads; stride % 4 == 0 keeps 16B alignment.
#define STR_POOL 132
#define STR_H1   1028
#define STR_H2   260
#define STR_H3   516

#define CP_ASYNC16(smem_u32, gptr) \
    asm volatile("cp.async.cg.shared.global [%0], [%1], 16;" \
                 :: "r"(smem_u32), "l"(gptr) : "memory")
#define CP_COMMIT() asm volatile("cp.async.commit_group;" ::: "memory")
#define CP_WAIT(n)  asm volatile("cp.async.wait_group %0;" :: "n"(n) : "memory")

// acc += hv (dot) w rows for 4 output cols
#define FMA4X4(acc, hv, w0, w1, w2, w3)                                   \
    do {                                                                  \
        acc.x += hv.x*w0.x + hv.y*w1.x + hv.z*w2.x + hv.w*w3.x;           \
        acc.y += hv.x*w0.y + hv.y*w1.y + hv.z*w2.y + hv.w*w3.y;           \
        acc.z += hv.x*w0.z + hv.y*w1.z + hv.z*w2.z + hv.w*w3.z;           \
        acc.w += hv.x*w0.w + hv.y*w1.w + hv.z*w2.w + hv.w*w3.w;           \
    } while (0)

__device__ __forceinline__ void mbar_arrive(int i) {
    __threadfence();
    __syncthreads();
    if (threadIdx.x == 0) atomicAdd(&g_bar2[i], 1u);
}
__device__ __forceinline__ void mbar_wait(int i) {
    if (threadIdx.x == 0) {
        volatile unsigned* p = &g_bar2[i];
        while (*p < MBLK) __nanosleep(32);
    }
    __syncthreads();
    __threadfence();
}

__global__ __launch_bounds__(MTPB) void mlp_kernel(
    const int*   __restrict__ cu,
    const float* __restrict__ w1, const float* __restrict__ b1,
    const float* __restrict__ w2, const float* __restrict__ b2,
    const float* __restrict__ w3, const float* __restrict__ b3,
    const float* __restrict__ w4, const float* __restrict__ b4,
    const float* __restrict__ w5, const float* __restrict__ b5,
    float* __restrict__ out)
{
    extern __shared__ float sm[];
    float* sw1   = sm + OFF_SW1;
    float* sw2   = sm + OFF_SW2;
    float* sw3   = sm + OFF_SW3;
    float* sw4   = sm + OFF_SW4;
    float* stage = sm + OFF_STAGE;
    float4* red4 = (float4*)(sm + OFF_RED);

    const int tid = threadIdx.x;
    const int mb  = blockIdx.x;

    // ---- weight preload: 4 commit groups, w1 first ------------------------
    {
        const unsigned s1 = (unsigned)__cvta_generic_to_shared(sw1);
        const unsigned s2 = (unsigned)__cvta_generic_to_shared(sw2);
        const unsigned s3 = (unsigned)__cvta_generic_to_shared(sw3);
        const unsigned s4 = (unsigned)__cvta_generic_to_shared(sw4);

        #pragma unroll
        for (int n = 0; n < 8; n++) {          // sw1: 2048 f4
            const int idx = tid + n * MTPB;
            const int r = idx >> 4, c = idx & 15;
            CP_ASYNC16(s1 + idx * 16, w1 + r * 1024 + mb * 64 + c * 4);
        }
        CP_COMMIT();                           // group 0 (sw1)
        #pragma unroll
        for (int n = 0; n < 16; n++) {         // sw2: 4096 f4
            const int idx = tid + n * MTPB;
            const int r = idx >> 2, c = idx & 3;
            CP_ASYNC16(s2 + idx * 16, w2 + r * 256 + mb * 16 + c * 4);
        }
        CP_COMMIT();                           // group 1 (sw2)
        #pragma unroll
        for (int n = 0; n < 8; n++) {          // sw3: 2048 f4
            const int idx = tid + n * MTPB;
            const int r = idx >> 3, c = idx & 7;
            CP_ASYNC16(s3 + idx * 16, w3 + r * 512 + mb * 32 + c * 4);
        }
        CP_COMMIT();                           // group 2 (sw3)
        #pragma unroll
        for (int n = 0; n < 4; n++) {          // sw4: 1024 f4
            const int idx = tid + n * MTPB;
            const int r = idx >> 1, c = idx & 1;
            CP_ASYNC16(s4 + idx * 16, w4 + r * 128 + mb * 8 + c * 4);
        }
        CP_COMMIT();                           // group 3 (sw4)
    }

    // ---- biases ----
    if (tid < 64) sm[OFF_B1 + tid] = b1[mb * 64 + tid];
    if (tid < 16) sm[OFF_B2 + tid] = b2[mb * 16 + tid];
    if (tid < 32) sm[OFF_B3 + tid] = b3[mb * 32 + tid];
    if (tid < 8)  sm[OFF_B4 + tid] = b4[mb * 8 + tid];

    // ---- pooled input: 1 float4/thread, padded stride ----
    {
        const float4 v = ((const float4*)g_sums)[tid];
        const int b = tid >> 5;
        const int m = tid & 31;
        const int cnt = cu[b + 1] - cu[b];
        const float c = 1.0f / (8.0f * (float)(cnt > 1 ? cnt : 1));
        float4 o; o.x = v.x * c; o.y = v.y * c; o.z = v.z * c; o.w = v.w * c;
        *(float4*)&stage[b * STR_POOL + m * 4] = o;
    }

    CP_WAIT(3);                                // sw1 ready
    __syncthreads();

    // ===== L1: pooled(8x128) -> h1 (8 x 64 cols), silu ====================
    // tid = cg(16) | b(8)<<4 | kc(2)<<7 ; k-range 64 per kc
    {
        const int cg = tid & 15, b = (tid >> 4) & 7, kc = tid >> 7;
        const float* hrow = &stage[b * STR_POOL + kc * 64];
        const float* wb   = &sw1[kc * 64 * 64 + cg * 4];
        float4 acc = make_float4(0.f, 0.f, 0.f, 0.f);
        #pragma unroll 4
        for (int k = 0; k < 64; k += 4) {
            const float4 hv = *(const float4*)&hrow[k];
            const float4 w0 = *(const float4*)&wb[(k + 0) * 64];
            const float4 wq1 = *(const float4*)&wb[(k + 1) * 64];
            const float4 wq2 = *(const float4*)&wb[(k + 2) * 64];
            const float4 wq3 = *(const float4*)&wb[(k + 3) * 64];
            FMA4X4(acc, hv, w0, wq1, wq2, wq3);
        }
        red4[tid] = acc;
        __syncthreads();
        if (tid < 128) {                       // (cg, b), sum 2 k-chunks
            const float4 r0 = red4[tid];
            const float4 r1 = red4[tid + 128];
            const int jc = (tid & 15) * 4;
            float4 o;
            o.x = silu_f(r0.x + r1.x + sm[OFF_B1 + jc + 0]);
            o.y = silu_f(r0.y + r1.y + sm[OFF_B1 + jc + 1]);
            o.z = silu_f(r0.z + r1.z + sm[OFF_B1 + jc + 2]);
            o.w = silu_f(r0.w + r1.w + sm[OFF_B1 + jc + 3]);
            const int b_ = (tid >> 4) & 7;
            *(float4*)&g_h1[b_ * 1024 + mb * 64 + jc] = o;
        }
    }
    mbar_arrive(0);
    mbar_wait(0);

    // ---- stage h1 (stride 1028) ----
    {
        const float4* src = (const float4*)g_h1;
        #pragma unroll
        for (int n = 0; n < 8; n++) {
            const int idx = tid + n * MTPB;    // 2048 f4
            const float4 v = src[idx];
            const int base = idx << 2;
            *(float4*)&stage[(base >> 10) * STR_H1 + (base & 1023)] = v;
        }
    }
    CP_WAIT(2);                                // sw2 ready
    __syncthreads();

    // ===== L2: h1 -> h2 (8 x 16 cols); tid = cg(4)|b(8)<<2|kc(8)<<5 =======
    {
        const int cg = tid & 3, b = (tid >> 2) & 7, kc = tid >> 5;
        const float* hrow = &stage[b * STR_H1 + kc * 128];
        const float* wb   = &sw2[kc * 128 * 16 + cg * 4];
        float4 acc = make_float4(0.f, 0.f, 0.f, 0.f);
        #pragma unroll 4
        for (int k = 0; k < 128; k += 4) {
            const float4 hv = *(const float4*)&hrow[k];
            const float4 w0 = *(const float4*)&wb[(k + 0) * 16];
            const float4 wq1 = *(const float4*)&wb[(k + 1) * 16];
            const float4 wq2 = *(const float4*)&wb[(k + 2) * 16];
            const float4 wq3 = *(const float4*)&wb[(k + 3) * 16];
            FMA4X4(acc, hv, w0, wq1, wq2, wq3);
        }
        red4[tid] = acc;
        __syncthreads();
        if (tid < 32) {                        // (cg, b), sum 8 k-chunks
            float4 s = red4[tid];
            #pragma unroll
            for (int c = 1; c < 8; c++) {
                const float4 r = red4[tid + 32 * c];
                s.x += r.x; s.y += r.y; s.z += r.z; s.w += r.w;
            }
            const int jc = (tid & 3) * 4;
            const int b_ = tid >> 2;
            float4 o;
            o.x = s.x + sm[OFF_B2 + jc + 0];
            o.y = s.y + sm[OFF_B2 + jc + 1];
            o.z = s.z + sm[OFF_B2 + jc + 2];
            o.w = s.w + sm[OFF_B2 + jc + 3];
            *(float4*)&g_h2[b_ * 256 + mb * 16 + jc] = o;
        }
    }
    mbar_arrive(1);
    mbar_wait(1);

    // ---- stage h2 (stride 260) ----
    {
        const float4* src = (const float4*)g_h2;
        #pragma unroll
        for (int n = 0; n < 2; n++) {
            const int idx = tid + n * MTPB;    // 512 f4
            const float4 v = src[idx];
            const int base = idx << 2;
            *(float4*)&stage[(base >> 8) * STR_H2 + (base & 255)] = v;
        }
    }
    CP_WAIT(1);                                // sw3 ready
    __syncthreads();

    // ===== L3: h2 -> h3 (8 x 32 cols), silu; tid = cg(8)|b(8)<<3|kc(4)<<6 =
    {
        const int cg = tid & 7, b = (tid >> 3) & 7, kc = tid >> 6;
        const float* hrow = &stage[b * STR_H2 + kc * 64];
        const float* wb   = &sw3[kc * 64 * 32 + cg * 4];
        float4 acc = make_float4(0.f, 0.f, 0.f, 0.f);
        #pragma unroll 4
        for (int k = 0; k < 64; k += 4) {
            const float4 hv = *(const float4*)&hrow[k];
            const float4 w0 = *(const float4*)&wb[(k + 0) * 32];
            const float4 wq1 = *(const float4*)&wb[(k + 1) * 32];
            const float4 wq2 = *(const float4*)&wb[(k + 2) * 32];
            const float4 wq3 = *(const float4*)&wb[(k + 3) * 32];
            FMA4X4(acc, hv, w0, wq1, wq2, wq3);
        }
        red4[tid] = acc;
        __syncthreads();
        if (tid < 64) {                        // (cg, b), sum 4 k-chunks
            float4 s = red4[tid];
            #pragma unroll
            for (int c = 1; c < 4; c++) {
                const float4 r = red4[tid + 64 * c];
                s.x += r.x; s.y += r.y; s.z += r.z; s.w += r.w;
            }
            const int jc = (tid & 7) * 4;
            const int b_ = tid >> 3;
            float4 o;
            o.x = silu_f(s.x + sm[OFF_B3 + jc + 0]);
            o.y = silu_f(s.y + sm[OFF_B3 + jc + 1]);
            o.z = silu_f(s.z + sm[OFF_B3 + jc + 2]);
            o.w = silu_f(s.w + sm[OFF_B3 + jc + 3]);
            *(float4*)&g_h3[b_ * 512 + mb * 32 + jc] = o;
        }
    }
    mbar_arrive(2);
    mbar_wait(2);

    // ---- stage h3 (stride 516) ----
    {
        const float4* src = (const float4*)g_h3;
        #pragma unroll
        for (int n = 0; n < 4; n++) {
            const int idx = tid + n * MTPB;    // 1024 f4
            const float4 v = src[idx];
            const int base = idx << 2;
            *(float4*)&stage[(base >> 9) * STR_H3 + (base & 511)] = v;
        }
    }
    CP_WAIT(0);                                // sw4 ready
    __syncthreads();

    // ===== L4: h3 -> h4 (8 x 8 cols), silu deferred; cg(2)|b(8)<<1|kc(16)<<4
    {
        const int cg = tid & 1, b = (tid >> 1) & 7, kc = tid >> 4;
        const float* hrow = &stage[b * STR_H3 + kc * 32];
        const float* wb   = &sw4[kc * 32 * 8 + cg * 4];
        float4 acc = make_float4(0.f, 0.f, 0.f, 0.f);
        #pragma unroll 4
        for (int k = 0; k < 32; k += 4) {
            const float4 hv = *(const float4*)&hrow[k];
            const float4 w0 = *(const float4*)&wb[(k + 0) * 8];
            const float4 wq1 = *(const float4*)&wb[(k + 1) * 8];
            const float4 wq2 = *(const float4*)&wb[(k + 2) * 8];
            const float4 wq3 = *(const float4*)&wb[(k + 3) * 8];
            FMA4X4(acc, hv, w0, wq1, wq2, wq3);
        }
        red4[tid] = acc;
        __syncthreads();
        if (tid < 16) {                        // (cg, b), sum 16 k-chunks
            float4 s = red4[tid];
            #pragma unroll
            for (int c = 1; c < 16; c++) {
                const float4 r = red4[tid + 16 * c];
                s.x += r.x; s.y += r.y; s.z += r.z; s.w += r.w;
            }
            const int jc = (tid & 1) * 4;
            const int b_ = tid >> 1;
            float4 o;
            o.x = s.x + sm[OFF_B4 + jc + 0];
            o.y = s.y + sm[OFF_B4 + jc + 1];
            o.z = s.z + sm[OFF_B4 + jc + 2];
            o.w = s.w + sm[OFF_B4 + jc + 3];
            *(float4*)&g_h4[b_ * 128 + mb * 8 + jc] = o;
        }
    }
    mbar_arrive(3);                            // blocks 1..15 arrive and exit
    if (mb != 0) return;
    mbar_wait(3);                              // only block 0 ever waits here

    // ===== L5 (block 0): logits + hard routing =============================
    {
        float* sred0 = stage;                  // [8][128]
        float* sred1 = stage + 1024;           // [8][128]
        const int k  = tid & 127;
        const int bh = tid >> 7;               // batches {bh, bh+2, bh+4, bh+6}
        const float wa = w5[k * 2 + 0];
        const float wb = w5[k * 2 + 1];

        __syncthreads();
        #pragma unroll
        for (int i = 0; i < 4; i++) {
            const int b = bh + 2 * i;
            const float s = silu_f(g_h4[b * 128 + k]);
            sred0[b * 128 + k] = s * wa;
            sred1[b * 128 + k] = s * wb;
        }
        __syncthreads();

        for (int off = 64; off >= 1; off >>= 1) {
            if (k < off) {
                #pragma unroll
                for (int i = 0; i < 4; i++) {
                    const int b = bh + 2 * i;
                    sred0[b * 128 + k] += sred0[b * 128 + k + off];
                    sred1[b * 128 + k] += sred1[b * 128 + k + off];
                }
            }
            __syncthreads();
        }

        if (k == 0) {
            const float bz0 = b5[0], bz1 = b5[1];
            #pragma unroll
            for (int i = 0; i < 4; i++) {
                const int b = bh + 2 * i;
                const float l0 = sred0[b * 128] + bz0;
                const float l1 = sred1[b * 128] + bz1;
                const float z  = (l1 > l0) ? 1.0f : 0.0f;
                #pragma unroll
                for (int h = 0; h < H_HEAD; h++)
                    out[b * H_HEAD + h] = z;
            }
        }
    }

    // ---- restore entry invariants (block 0 only; all others exited) -------
    __syncthreads();
    for (int i = tid; i < B_SEG * D_DIM; i += MTPB) g_sums[i] = 0.0f;
    if (tid < 4) g_bar2[tid] = 0u;
}

// ---------------------------------------------------------------------------
// Launch: 2 graph nodes
// ---------------------------------------------------------------------------
extern "C" void kernel_launch(void* const* d_in, const int* in_sizes, int n_in,
                              void* d_out, int out_size)
{
    const float* x  = (const float*)d_in[0];
    const int*   cu = (const int*)  d_in[1];
    const float* w1 = (const float*)d_in[2];
    const float* b1 = (const float*)d_in[3];
    const float* w2 = (const float*)d_in[4];
    const float* b2 = (const float*)d_in[5];
    const float* w3 = (const float*)d_in[6];
    const float* b3 = (const float*)d_in[7];
    const float* w4 = (const float*)d_in[8];
    const float* b4 = (const float*)d_in[9];
    const float* w5 = (const float*)d_in[10];
    const float* b5 = (const float*)d_in[11];
    float* out = (float*)d_out;

    cudaFuncSetAttribute(mlp_kernel,
                         cudaFuncAttributeMaxDynamicSharedMemorySize,
                         SMEM_MLP);

    segsum_kernel<<<SBLK, STPB>>>((const float4*)x, cu);
    mlp_kernel<<<MBLK, MTPB, SMEM_MLP>>>(cu, w1, b1, w2, b2, w3, b3,
                                         w4, b4, w5, b5, out);
}

// round 12
// speedup vs baseline: 2.0914x; 1.1009x over previous
#include <cuda_runtime.h>
#include <cuda_bf16.h>

// Problem constants
#define T_TOK   32768
#define B_SEG   8
#define H_HEAD  8
#define D_DIM   128
#define HD      (H_HEAD * D_DIM)   // 1024 floats per token row

// Segsum geometry
#define SBLK    2048
#define STPB    256
#define TOKS    (T_TOK / SBLK)     // 16 tokens per block

// MLP geometry: 16 CTAs = ONE cluster (non-portable size, allowed on sm_103a)
#define MBLK    16
#define MTPB    256

// Scratch (device globals; g_sums restored to zero by the MLP kernel's
// block 0 at the end of every call -> entry invariant holds every replay).
__device__ float    g_sums[B_SEG * D_DIM];
__device__ float    g_h1[B_SEG * 1024];
__device__ float    g_h2[B_SEG * 256];
__device__ float    g_h3[B_SEG * 512];
__device__ float    g_h4[B_SEG * 128];

__device__ __forceinline__ float silu_f(float x) {
    return x / (1.0f + __expf(-x));
}

// ===========================================================================
// Kernel 1: segment + head sum.  g_sums[b][d] = sum_{t in seg b} sum_h x[t,h,d]
// ===========================================================================
__global__ __launch_bounds__(STPB) void segsum_kernel(
    const float4* __restrict__ x, const int* __restrict__ cu)
{
    __shared__ float ssum[B_SEG * D_DIM];
    __shared__ int   touched[B_SEG];

    const int tid = threadIdx.x;
    const int bid = blockIdx.x;

    for (int i = tid; i < B_SEG * D_DIM; i += STPB) ssum[i] = 0.0f;
    if (tid < B_SEG) touched[tid] = 0;
    __syncthreads();

    const int c1 = cu[1], c2 = cu[2], c3 = cu[3], c4 = cu[4];
    const int c5 = cu[5], c6 = cu[6], c7 = cu[7];

    const int t0    = bid * TOKS;
    const int dbase = (4 * tid) & (D_DIM - 1);

    #define SEGOF(t) ((int)(((t) >= c1) + ((t) >= c2) + ((t) >= c3) + \
                            ((t) >= c4) + ((t) >= c5) + ((t) >= c6) + \
                            ((t) >= c7)))

    const int seg_lo = SEGOF(t0);
    const int seg_hi = SEGOF(t0 + TOKS - 1);

    if (seg_lo == seg_hi) {
        const float4* px = x + (size_t)t0 * (HD / 4) + tid;
        float a0 = 0.f, a1 = 0.f, a2 = 0.f, a3 = 0.f;
        #pragma unroll 1
        for (int g = 0; g < TOKS; g += 8) {
            float4 v0 = __ldcs(px + (size_t)(g + 0) * (HD / 4));
            float4 v1 = __ldcs(px + (size_t)(g + 1) * (HD / 4));
            float4 v2 = __ldcs(px + (size_t)(g + 2) * (HD / 4));
            float4 v3 = __ldcs(px + (size_t)(g + 3) * (HD / 4));
            float4 v4 = __ldcs(px + (size_t)(g + 4) * (HD / 4));
            float4 v5 = __ldcs(px + (size_t)(g + 5) * (HD / 4));
            float4 v6 = __ldcs(px + (size_t)(g + 6) * (HD / 4));
            float4 v7 = __ldcs(px + (size_t)(g + 7) * (HD / 4));
            a0 += ((v0.x + v1.x) + (v2.x + v3.x)) + ((v4.x + v5.x) + (v6.x + v7.x));
            a1 += ((v0.y + v1.y) + (v2.y + v3.y)) + ((v4.y + v5.y) + (v6.y + v7.y));
            a2 += ((v0.z + v1.z) + (v2.z + v3.z)) + ((v4.z + v5.z) + (v6.z + v7.z));
            a3 += ((v0.w + v1.w) + (v2.w + v3.w)) + ((v4.w + v5.w) + (v6.w + v7.w));
        }
        atomicAdd(&ssum[seg_lo * D_DIM + dbase + 0], a0);
        atomicAdd(&ssum[seg_lo * D_DIM + dbase + 1], a1);
        atomicAdd(&ssum[seg_lo * D_DIM + dbase + 2], a2);
        atomicAdd(&ssum[seg_lo * D_DIM + dbase + 3], a3);
        if (tid == 0) touched[seg_lo] = 1;
    } else {
        float a0 = 0.f, a1 = 0.f, a2 = 0.f, a3 = 0.f;
        int curseg = -1;
        for (int tt = 0; tt < TOKS; tt++) {
            const int t = t0 + tt;
            const int seg = SEGOF(t);
            if (seg != curseg) {
                if (curseg >= 0) {
                    atomicAdd(&ssum[curseg * D_DIM + dbase + 0], a0);
                    atomicAdd(&ssum[curseg * D_DIM + dbase + 1], a1);
                    atomicAdd(&ssum[curseg * D_DIM + dbase + 2], a2);
                    atomicAdd(&ssum[curseg * D_DIM + dbase + 3], a3);
                    touched[curseg] = 1;
                }
                curseg = seg;
                a0 = a1 = a2 = a3 = 0.f;
            }
            float4 v = __ldcs(&x[(size_t)t * (HD / 4) + tid]);
            a0 += v.x; a1 += v.y; a2 += v.z; a3 += v.w;
        }
        if (curseg >= 0) {
            atomicAdd(&ssum[curseg * D_DIM + dbase + 0], a0);
            atomicAdd(&ssum[curseg * D_DIM + dbase + 1], a1);
            atomicAdd(&ssum[curseg * D_DIM + dbase + 2], a2);
            atomicAdd(&ssum[curseg * D_DIM + dbase + 3], a3);
            touched[curseg] = 1;
        }
    }
    #undef SEGOF
    __syncthreads();

    for (int s = 0; s < B_SEG; s++) {
        if (touched[s]) {
            for (int i = tid; i < D_DIM; i += STPB)
                atomicAdd(&g_sums[s * D_DIM + i], ssum[s * D_DIM + i]);
        }
    }
}

// ===========================================================================
// Kernel 2: MLP as ONE 16-CTA cluster. Inter-layer sync = barrier.cluster
// (~0.25us vs ~3us for a global-atomic barrier). Weights cp.async'd in 4
// commit groups; activations staged in global (L2) with padded-smem copies.
// Block mb owns cols: w1[.,mb*64+64) w2[.,mb*16+16) w3[.,mb*32+32) w4[.,mb*8+8)
// ===========================================================================

#define OFF_SW1   0        //  8192 (128 x 64)
#define OFF_SW2   8192     // 16384 (1024 x 16)
#define OFF_SW3   24576    //  8192 (256 x 32)
#define OFF_SW4   32768    //  4096 (512 x 8)
#define OFF_STAGE 36864    //  8320 (h1 at stride 1028 max; L5 uses 2048)
#define OFF_RED   45184    //  1024 (256 x float4)
#define OFF_B1    46208    //    64
#define OFF_B2    46272    //    16
#define OFF_B3    46288    //    32
#define OFF_B4    46320    //     8
#define SMEM_FLOATS 46336
#define SMEM_MLP (SMEM_FLOATS * 4)   // 185344 bytes

#define STR_POOL 132
#define STR_H1   1028
#define STR_H2   260
#define STR_H3   516

#define CP_ASYNC16(smem_u32, gptr) \
    asm volatile("cp.async.cg.shared.global [%0], [%1], 16;" \
                 :: "r"(smem_u32), "l"(gptr) : "memory")
#define CP_COMMIT() asm volatile("cp.async.commit_group;" ::: "memory")
#define CP_WAIT(n)  asm volatile("cp.async.wait_group %0;" :: "n"(n) : "memory")

#define FMA4X4(acc, hv, w0, w1, w2, w3)                                   \
    do {                                                                  \
        acc.x += hv.x*w0.x + hv.y*w1.x + hv.z*w2.x + hv.w*w3.x;           \
        acc.y += hv.x*w0.y + hv.y*w1.y + hv.z*w2.y + hv.w*w3.y;           \
        acc.z += hv.x*w0.z + hv.y*w1.z + hv.z*w2.z + hv.w*w3.z;           \
        acc.w += hv.x*w0.w + hv.y*w1.w + hv.z*w2.w + hv.w*w3.w;           \
    } while (0)

// Full cluster barrier: order my global writes (release via fence), then
// arrive+wait. HW phase-tracked — reusable, no state to reset.
__device__ __forceinline__ void cluster_bar() {
    __threadfence();
    asm volatile("barrier.cluster.arrive.aligned;" ::: "memory");
    asm volatile("barrier.cluster.wait.aligned;" ::: "memory");
}

__global__ __launch_bounds__(MTPB) __cluster_dims__(MBLK, 1, 1)
void mlp_kernel(
    const int*   __restrict__ cu,
    const float* __restrict__ w1, const float* __restrict__ b1,
    const float* __restrict__ w2, const float* __restrict__ b2,
    const float* __restrict__ w3, const float* __restrict__ b3,
    const float* __restrict__ w4, const float* __restrict__ b4,
    const float* __restrict__ w5, const float* __restrict__ b5,
    float* __restrict__ out)
{
    extern __shared__ float sm[];
    float* sw1   = sm + OFF_SW1;
    float* sw2   = sm + OFF_SW2;
    float* sw3   = sm + OFF_SW3;
    float* sw4   = sm + OFF_SW4;
    float* stage = sm + OFF_STAGE;
    float4* red4 = (float4*)(sm + OFF_RED);

    const int tid = threadIdx.x;
    const int mb  = blockIdx.x;

    // ---- weight preload: 4 commit groups, w1 first ------------------------
    {
        const unsigned s1 = (unsigned)__cvta_generic_to_shared(sw1);
        const unsigned s2 = (unsigned)__cvta_generic_to_shared(sw2);
        const unsigned s3 = (unsigned)__cvta_generic_to_shared(sw3);
        const unsigned s4 = (unsigned)__cvta_generic_to_shared(sw4);

        #pragma unroll
        for (int n = 0; n < 8; n++) {          // sw1: 2048 f4
            const int idx = tid + n * MTPB;
            const int r = idx >> 4, c = idx & 15;
            CP_ASYNC16(s1 + idx * 16, w1 + r * 1024 + mb * 64 + c * 4);
        }
        CP_COMMIT();
        #pragma unroll
        for (int n = 0; n < 16; n++) {         // sw2: 4096 f4
            const int idx = tid + n * MTPB;
            const int r = idx >> 2, c = idx & 3;
            CP_ASYNC16(s2 + idx * 16, w2 + r * 256 + mb * 16 + c * 4);
        }
        CP_COMMIT();
        #pragma unroll
        for (int n = 0; n < 8; n++) {          // sw3: 2048 f4
            const int idx = tid + n * MTPB;
            const int r = idx >> 3, c = idx & 7;
            CP_ASYNC16(s3 + idx * 16, w3 + r * 512 + mb * 32 + c * 4);
        }
        CP_COMMIT();
        #pragma unroll
        for (int n = 0; n < 4; n++) {          // sw4: 1024 f4
            const int idx = tid + n * MTPB;
            const int r = idx >> 1, c = idx & 1;
            CP_ASYNC16(s4 + idx * 16, w4 + r * 128 + mb * 8 + c * 4);
        }
        CP_COMMIT();
    }

    // ---- biases ----
    if (tid < 64) sm[OFF_B1 + tid] = b1[mb * 64 + tid];
    if (tid < 16) sm[OFF_B2 + tid] = b2[mb * 16 + tid];
    if (tid < 32) sm[OFF_B3 + tid] = b3[mb * 32 + tid];
    if (tid < 8)  sm[OFF_B4 + tid] = b4[mb * 8 + tid];

    // ---- pooled input: 1 float4/thread, padded stride ----
    {
        const float4 v = ((const float4*)g_sums)[tid];
        const int b = tid >> 5;
        const int m = tid & 31;
        const int cnt = cu[b + 1] - cu[b];
        const float c = 1.0f / (8.0f * (float)(cnt > 1 ? cnt : 1));
        float4 o; o.x = v.x * c; o.y = v.y * c; o.z = v.z * c; o.w = v.w * c;
        *(float4*)&stage[b * STR_POOL + m * 4] = o;
    }

    CP_WAIT(3);                                // sw1 ready
    __syncthreads();

    // ===== L1: pooled(8x128) -> h1 (8 x 64 cols), silu ====================
    {
        const int cg = tid & 15, b = (tid >> 4) & 7, kc = tid >> 7;
        const float* hrow = &stage[b * STR_POOL + kc * 64];
        const float* wb   = &sw1[kc * 64 * 64 + cg * 4];
        float4 acc = make_float4(0.f, 0.f, 0.f, 0.f);
        #pragma unroll 4
        for (int k = 0; k < 64; k += 4) {
            const float4 hv = *(const float4*)&hrow[k];
            const float4 w0 = *(const float4*)&wb[(k + 0) * 64];
            const float4 wq1 = *(const float4*)&wb[(k + 1) * 64];
            const float4 wq2 = *(const float4*)&wb[(k + 2) * 64];
            const float4 wq3 = *(const float4*)&wb[(k + 3) * 64];
            FMA4X4(acc, hv, w0, wq1, wq2, wq3);
        }
        red4[tid] = acc;
        __syncthreads();
        if (tid < 128) {
            const float4 r0 = red4[tid];
            const float4 r1 = red4[tid + 128];
            const int jc = (tid & 15) * 4;
            float4 o;
            o.x = silu_f(r0.x + r1.x + sm[OFF_B1 + jc + 0]);
            o.y = silu_f(r0.y + r1.y + sm[OFF_B1 + jc + 1]);
            o.z = silu_f(r0.z + r1.z + sm[OFF_B1 + jc + 2]);
            o.w = silu_f(r0.w + r1.w + sm[OFF_B1 + jc + 3]);
            const int b_ = (tid >> 4) & 7;
            *(float4*)&g_h1[b_ * 1024 + mb * 64 + jc] = o;
        }
    }
    cluster_bar();                             // (1) h1 visible cluster-wide

    // ---- stage h1 (stride 1028) ----
    {
        const float4* src = (const float4*)g_h1;
        #pragma unroll
        for (int n = 0; n < 8; n++) {
            const int idx = tid + n * MTPB;    // 2048 f4
            const float4 v = src[idx];
            const int base = idx << 2;
            *(float4*)&stage[(base >> 10) * STR_H1 + (base & 1023)] = v;
        }
    }
    CP_WAIT(2);                                // sw2 ready
    __syncthreads();

    // ===== L2: h1 -> h2 (8 x 16 cols) =====================================
    {
        const int cg = tid & 3, b = (tid >> 2) & 7, kc = tid >> 5;
        const float* hrow = &stage[b * STR_H1 + kc * 128];
        const float* wb   = &sw2[kc * 128 * 16 + cg * 4];
        float4 acc = make_float4(0.f, 0.f, 0.f, 0.f);
        #pragma unroll 4
        for (int k = 0; k < 128; k += 4) {
            const float4 hv = *(const float4*)&hrow[k];
            const float4 w0 = *(const float4*)&wb[(k + 0) * 16];
            const float4 wq1 = *(const float4*)&wb[(k + 1) * 16];
            const float4 wq2 = *(const float4*)&wb[(k + 2) * 16];
            const float4 wq3 = *(const float4*)&wb[(k + 3) * 16];
            FMA4X4(acc, hv, w0, wq1, wq2, wq3);
        }
        red4[tid] = acc;
        __syncthreads();
        if (tid < 32) {
            float4 s = red4[tid];
            #pragma unroll
            for (int c = 1; c < 8; c++) {
                const float4 r = red4[tid + 32 * c];
                s.x += r.x; s.y += r.y; s.z += r.z; s.w += r.w;
            }
            const int jc = (tid & 3) * 4;
            const int b_ = tid >> 2;
            float4 o;
            o.x = s.x + sm[OFF_B2 + jc + 0];
            o.y = s.y + sm[OFF_B2 + jc + 1];
            o.z = s.z + sm[OFF_B2 + jc + 2];
            o.w = s.w + sm[OFF_B2 + jc + 3];
            *(float4*)&g_h2[b_ * 256 + mb * 16 + jc] = o;
        }
    }
    cluster_bar();                             // (2) h2 visible cluster-wide

    // ---- stage h2 (stride 260) ----
    {
        const float4* src = (const float4*)g_h2;
        #pragma unroll
        for (int n = 0; n < 2; n++) {
            const int idx = tid + n * MTPB;    // 512 f4
            const float4 v = src[idx];
            const int base = idx << 2;
            *(float4*)&stage[(base >> 8) * STR_H2 + (base & 255)] = v;
        }
    }
    CP_WAIT(1);                                // sw3 ready
    __syncthreads();

    // ===== L3: h2 -> h3 (8 x 32 cols), silu ===============================
    {
        const int cg = tid & 7, b = (tid >> 3) & 7, kc = tid >> 6;
        const float* hrow = &stage[b * STR_H2 + kc * 64];
        const float* wb   = &sw3[kc * 64 * 32 + cg * 4];
        float4 acc = make_float4(0.f, 0.f, 0.f, 0.f);
        #pragma unroll 4
        for (int k = 0; k < 64; k += 4) {
            const float4 hv = *(const float4*)&hrow[k];
            const float4 w0 = *(const float4*)&wb[(k + 0) * 32];
            const float4 wq1 = *(const float4*)&wb[(k + 1) * 32];
            const float4 wq2 = *(const float4*)&wb[(k + 2) * 32];
            const float4 wq3 = *(const float4*)&wb[(k + 3) * 32];
            FMA4X4(acc, hv, w0, wq1, wq2, wq3);
        }
        red4[tid] = acc;
        __syncthreads();
        if (tid < 64) {
            float4 s = red4[tid];
            #pragma unroll
            for (int c = 1; c < 4; c++) {
                const float4 r = red4[tid + 64 * c];
                s.x += r.x; s.y += r.y; s.z += r.z; s.w += r.w;
            }
            const int jc = (tid & 7) * 4;
            const int b_ = tid >> 3;
            float4 o;
            o.x = silu_f(s.x + sm[OFF_B3 + jc + 0]);
            o.y = silu_f(s.y + sm[OFF_B3 + jc + 1]);
            o.z = silu_f(s.z + sm[OFF_B3 + jc + 2]);
            o.w = silu_f(s.w + sm[OFF_B3 + jc + 3]);
            *(float4*)&g_h3[b_ * 512 + mb * 32 + jc] = o;
        }
    }
    cluster_bar();                             // (3) h3 visible cluster-wide

    // ---- stage h3 (stride 516) ----
    {
        const float4* src = (const float4*)g_h3;
        #pragma unroll
        for (int n = 0; n < 4; n++) {
            const int idx = tid + n * MTPB;    // 1024 f4
            const float4 v = src[idx];
            const int base = idx << 2;
            *(float4*)&stage[(base >> 9) * STR_H3 + (base & 511)] = v;
        }
    }
    CP_WAIT(0);                                // sw4 ready
    __syncthreads();

    // ===== L4: h3 -> h4 (8 x 8 cols), silu deferred =======================
    {
        const int cg = tid & 1, b = (tid >> 1) & 7, kc = tid >> 4;
        const float* hrow = &stage[b * STR_H3 + kc * 32];
        const float* wb   = &sw4[kc * 32 * 8 + cg * 4];
        float4 acc = make_float4(0.f, 0.f, 0.f, 0.f);
        #pragma unroll 4
        for (int k = 0; k < 32; k += 4) {
            const float4 hv = *(const float4*)&hrow[k];
            const float4 w0 = *(const float4*)&wb[(k + 0) * 8];
            const float4 wq1 = *(const float4*)&wb[(k + 1) * 8];
            const float4 wq2 = *(const float4*)&wb[(k + 2) * 8];
            const float4 wq3 = *(const float4*)&wb[(k + 3) * 8];
            FMA4X4(acc, hv, w0, wq1, wq2, wq3);
        }
        red4[tid] = acc;
        __syncthreads();
        if (tid < 16) {
            float4 s = red4[tid];
            #pragma unroll
            for (int c = 1; c < 16; c++) {
                const float4 r = red4[tid + 16 * c];
                s.x += r.x; s.y += r.y; s.z += r.z; s.w += r.w;
            }
            const int jc = (tid & 1) * 4;
            const int b_ = tid >> 1;
            float4 o;
            o.x = s.x + sm[OFF_B4 + jc + 0];
            o.y = s.y + sm[OFF_B4 + jc + 1];
            o.z = s.z + sm[OFF_B4 + jc + 2];
            o.w = s.w + sm[OFF_B4 + jc + 3];
            *(float4*)&g_h4[b_ * 128 + mb * 8 + jc] = o;
        }
    }

    // ===== Final barrier: blocks 1..15 arrive + exit; block 0 waits =======
    __threadfence();
    asm volatile("barrier.cluster.arrive.aligned;" ::: "memory");
    if (mb != 0) return;
    asm volatile("barrier.cluster.wait.aligned;" ::: "memory");

    // ===== L5 (block 0): logits + hard routing =============================
    {
        float* sred0 = stage;                  // [8][128]
        float* sred1 = stage + 1024;           // [8][128]
        const int k  = tid & 127;
        const int bh = tid >> 7;               // batches {bh, bh+2, bh+4, bh+6}
        const float wa = w5[k * 2 + 0];
        const float wb = w5[k * 2 + 1];

        __syncthreads();
        #pragma unroll
        for (int i = 0; i < 4; i++) {
            const int b = bh + 2 * i;
            const float s = silu_f(g_h4[b * 128 + k]);
            sred0[b * 128 + k] = s * wa;
            sred1[b * 128 + k] = s * wb;
        }
        __syncthreads();

        for (int off = 64; off >= 1; off >>= 1) {
            if (k < off) {
                #pragma unroll
                for (int i = 0; i < 4; i++) {
                    const int b = bh + 2 * i;
                    sred0[b * 128 + k] += sred0[b * 128 + k + off];
                    sred1[b * 128 + k] += sred1[b * 128 + k + off];
                }
            }
            __syncthreads();
        }

        if (k == 0) {
            const float bz0 = b5[0], bz1 = b5[1];
            #pragma unroll
            for (int i = 0; i < 4; i++) {
                const int b = bh + 2 * i;
                const float l0 = sred0[b * 128] + bz0;
                const float l1 = sred1[b * 128] + bz1;
                const float z  = (l1 > l0) ? 1.0f : 0.0f;
                #pragma unroll
                for (int h = 0; h < H_HEAD; h++)
                    out[b * H_HEAD + h] = z;
            }
        }
    }

    // ---- restore entry invariant for g_sums (block 0 only) ----------------
    __syncthreads();
    for (int i = tid; i < B_SEG * D_DIM; i += MTPB) g_sums[i] = 0.0f;
}

// ---------------------------------------------------------------------------
// Launch: 2 graph nodes
// ---------------------------------------------------------------------------
extern "C" void kernel_launch(void* const* d_in, const int* in_sizes, int n_in,
                              void* d_out, int out_size)
{
    const float* x  = (const float*)d_in[0];
    const int*   cu = (const int*)  d_in[1];
    const float* w1 = (const float*)d_in[2];
    const float* b1 = (const float*)d_in[3];
    const float* w2 = (const float*)d_in[4];
    const float* b2 = (const float*)d_in[5];
    const float* w3 = (const float*)d_in[6];
    const float* b3 = (const float*)d_in[7];
    const float* w4 = (const float*)d_in[8];
    const float* b4 = (const float*)d_in[9];
    const float* w5 = (const float*)d_in[10];
    const float* b5 = (const float*)d_in[11];
    float* out = (float*)d_out;

    cudaFuncSetAttribute(mlp_kernel,
                         cudaFuncAttributeMaxDynamicSharedMemorySize,
                         SMEM_MLP);
    cudaFuncSetAttribute(mlp_kernel,
                         cudaFuncAttributeNonPortableClusterSizeAllowed, 1);

    segsum_kernel<<<SBLK, STPB>>>((const float4*)x, cu);
    mlp_kernel<<<MBLK, MTPB, SMEM_MLP>>>(cu, w1, b1, w2, b2, w3, b3,
                                         w4, b4, w5, b5, out);
}

// round 13
// speedup vs baseline: 2.2076x; 1.0556x over previous
#include <cuda_runtime.h>
#include <cuda_bf16.h>

// Problem constants
#define T_TOK   32768
#define B_SEG   8
#define H_HEAD  8
#define D_DIM   128
#define HD      (H_HEAD * D_DIM)   // 1024 floats per token row

// Segsum geometry
#define SBLK    2048
#define STPB    256
#define TOKS    (T_TOK / SBLK)     // 16 tokens per block

// MLP geometry: 16 CTAs = ONE cluster (non-portable size, allowed on sm_103a)
#define MBLK    16
#define MTPB    256

// Scratch (device globals; g_sums restored to zero by the MLP kernel's
// block 0 at the end of every call -> entry invariant holds every replay).
__device__ float    g_sums[B_SEG * D_DIM];
__device__ float    g_h1[B_SEG * 1024];
__device__ float    g_h2[B_SEG * 256];
__device__ float    g_h3[B_SEG * 512];
__device__ float    g_h4[B_SEG * 128];

__device__ __forceinline__ float silu_f(float x) {
    return x / (1.0f + __expf(-x));
}

// ===========================================================================
// Kernel 1: segment + head sum.  g_sums[b][d] = sum_{t in seg b} sum_h x[t,h,d]
// Fires the PDL trigger immediately so the MLP kernel can launch and prefetch
// its weights while this kernel streams the 128 MB input.
// ===========================================================================
__global__ __launch_bounds__(STPB) void segsum_kernel(
    const float4* __restrict__ x, const int* __restrict__ cu)
{
    // Let dependent (mlp_kernel) begin launching now; it still does
    // griddepcontrol.wait (full completion + visibility) before reading g_sums.
    asm volatile("griddepcontrol.launch_dependents;");

    __shared__ float ssum[B_SEG * D_DIM];
    __shared__ int   touched[B_SEG];

    const int tid = threadIdx.x;
    const int bid = blockIdx.x;

    for (int i = tid; i < B_SEG * D_DIM; i += STPB) ssum[i] = 0.0f;
    if (tid < B_SEG) touched[tid] = 0;
    __syncthreads();

    const int c1 = cu[1], c2 = cu[2], c3 = cu[3], c4 = cu[4];
    const int c5 = cu[5], c6 = cu[6], c7 = cu[7];

    const int t0    = bid * TOKS;
    const int dbase = (4 * tid) & (D_DIM - 1);

    #define SEGOF(t) ((int)(((t) >= c1) + ((t) >= c2) + ((t) >= c3) + \
                            ((t) >= c4) + ((t) >= c5) + ((t) >= c6) + \
                            ((t) >= c7)))

    const int seg_lo = SEGOF(t0);
    const int seg_hi = SEGOF(t0 + TOKS - 1);

    if (seg_lo == seg_hi) {
        const float4* px = x + (size_t)t0 * (HD / 4) + tid;
        float a0 = 0.f, a1 = 0.f, a2 = 0.f, a3 = 0.f;
        #pragma unroll 1
        for (int g = 0; g < TOKS; g += 8) {
            float4 v0 = __ldcs(px + (size_t)(g + 0) * (HD / 4));
            float4 v1 = __ldcs(px + (size_t)(g + 1) * (HD / 4));
            float4 v2 = __ldcs(px + (size_t)(g + 2) * (HD / 4));
            float4 v3 = __ldcs(px + (size_t)(g + 3) * (HD / 4));
            float4 v4 = __ldcs(px + (size_t)(g + 4) * (HD / 4));
            float4 v5 = __ldcs(px + (size_t)(g + 5) * (HD / 4));
            float4 v6 = __ldcs(px + (size_t)(g + 6) * (HD / 4));
            float4 v7 = __ldcs(px + (size_t)(g + 7) * (HD / 4));
            a0 += ((v0.x + v1.x) + (v2.x + v3.x)) + ((v4.x + v5.x) + (v6.x + v7.x));
            a1 += ((v0.y + v1.y) + (v2.y + v3.y)) + ((v4.y + v5.y) + (v6.y + v7.y));
            a2 += ((v0.z + v1.z) + (v2.z + v3.z)) + ((v4.z + v5.z) + (v6.z + v7.z));
            a3 += ((v0.w + v1.w) + (v2.w + v3.w)) + ((v4.w + v5.w) + (v6.w + v7.w));
        }
        atomicAdd(&ssum[seg_lo * D_DIM + dbase + 0], a0);
        atomicAdd(&ssum[seg_lo * D_DIM + dbase + 1], a1);
        atomicAdd(&ssum[seg_lo * D_DIM + dbase + 2], a2);
        atomicAdd(&ssum[seg_lo * D_DIM + dbase + 3], a3);
        if (tid == 0) touched[seg_lo] = 1;
    } else {
        float a0 = 0.f, a1 = 0.f, a2 = 0.f, a3 = 0.f;
        int curseg = -1;
        for (int tt = 0; tt < TOKS; tt++) {
            const int t = t0 + tt;
            const int seg = SEGOF(t);
            if (seg != curseg) {
                if (curseg >= 0) {
                    atomicAdd(&ssum[curseg * D_DIM + dbase + 0], a0);
                    atomicAdd(&ssum[curseg * D_DIM + dbase + 1], a1);
                    atomicAdd(&ssum[curseg * D_DIM + dbase + 2], a2);
                    atomicAdd(&ssum[curseg * D_DIM + dbase + 3], a3);
                    touched[curseg] = 1;
                }
                curseg = seg;
                a0 = a1 = a2 = a3 = 0.f;
            }
            float4 v = __ldcs(&x[(size_t)t * (HD / 4) + tid]);
            a0 += v.x; a1 += v.y; a2 += v.z; a3 += v.w;
        }
        if (curseg >= 0) {
            atomicAdd(&ssum[curseg * D_DIM + dbase + 0], a0);
            atomicAdd(&ssum[curseg * D_DIM + dbase + 1], a1);
            atomicAdd(&ssum[curseg * D_DIM + dbase + 2], a2);
            atomicAdd(&ssum[curseg * D_DIM + dbase + 3], a3);
            touched[curseg] = 1;
        }
    }
    #undef SEGOF
    __syncthreads();

    for (int s = 0; s < B_SEG; s++) {
        if (touched[s]) {
            for (int i = tid; i < D_DIM; i += STPB)
                atomicAdd(&g_sums[s * D_DIM + i], ssum[s * D_DIM + i]);
        }
    }
}

// ===========================================================================
// Kernel 2: MLP, one 16-CTA cluster, launched via PDL. Weight cp.asyncs and
// bias loads execute WHILE segsum is still streaming; griddepcontrol.wait
// gates only the g_sums consumption. Inter-layer sync = barrier.cluster.
// Block mb owns cols: w1[.,mb*64+64) w2[.,mb*16+16) w3[.,mb*32+32) w4[.,mb*8+8)
// ===========================================================================

#define OFF_SW1   0        //  8192 (128 x 64)
#define OFF_SW2   8192     // 16384 (1024 x 16)
#define OFF_SW3   24576    //  8192 (256 x 32)
#define OFF_SW4   32768    //  4096 (512 x 8)
#define OFF_STAGE 36864    //  8320 (h1 at stride 1028 max; L5 uses 2048)
#define OFF_RED   45184    //  1024 (256 x float4)
#define OFF_B1    46208    //    64
#define OFF_B2    46272    //    16
#define OFF_B3    46288    //    32
#define OFF_B4    46320    //     8
#define SMEM_FLOATS 46336
#define SMEM_MLP (SMEM_FLOATS * 4)   // 185344 bytes

#define STR_POOL 132
#define STR_H1   1028
#define STR_H2   260
#define STR_H3   516

#define CP_ASYNC16(smem_u32, gptr) \
    asm volatile("cp.async.cg.shared.global [%0], [%1], 16;" \
                 :: "r"(smem_u32), "l"(gptr) : "memory")
#define CP_COMMIT() asm volatile("cp.async.commit_group;" ::: "memory")
#define CP_WAIT(n)  asm volatile("cp.async.wait_group %0;" :: "n"(n) : "memory")

#define FMA4X4(acc, hv, w0, w1, w2, w3)                                   \
    do {                                                                  \
        acc.x += hv.x*w0.x + hv.y*w1.x + hv.z*w2.x + hv.w*w3.x;           \
        acc.y += hv.x*w0.y + hv.y*w1.y + hv.z*w2.y + hv.w*w3.y;           \
        acc.z += hv.x*w0.z + hv.y*w1.z + hv.z*w2.z + hv.w*w3.z;           \
        acc.w += hv.x*w0.w + hv.y*w1.w + hv.z*w2.w + hv.w*w3.w;           \
    } while (0)

__device__ __forceinline__ void cluster_bar() {
    __threadfence();
    asm volatile("barrier.cluster.arrive.aligned;" ::: "memory");
    asm volatile("barrier.cluster.wait.aligned;" ::: "memory");
}

__global__ __launch_bounds__(MTPB) __cluster_dims__(MBLK, 1, 1)
void mlp_kernel(
    const int*   __restrict__ cu,
    const float* __restrict__ w1, const float* __restrict__ b1,
    const float* __restrict__ w2, const float* __restrict__ b2,
    const float* __restrict__ w3, const float* __restrict__ b3,
    const float* __restrict__ w4, const float* __restrict__ b4,
    const float* __restrict__ w5, const float* __restrict__ b5,
    float* __restrict__ out)
{
    extern __shared__ float sm[];
    float* sw1   = sm + OFF_SW1;
    float* sw2   = sm + OFF_SW2;
    float* sw3   = sm + OFF_SW3;
    float* sw4   = sm + OFF_SW4;
    float* stage = sm + OFF_STAGE;
    float4* red4 = (float4*)(sm + OFF_RED);

    const int tid = threadIdx.x;
    const int mb  = blockIdx.x;

    // ---- weight preload: issued BEFORE waiting on segsum (PDL overlap) ----
    {
        const unsigned s1 = (unsigned)__cvta_generic_to_shared(sw1);
        const unsigned s2 = (unsigned)__cvta_generic_to_shared(sw2);
        const unsigned s3 = (unsigned)__cvta_generic_to_shared(sw3);
        const unsigned s4 = (unsigned)__cvta_generic_to_shared(sw4);

        #pragma unroll
        for (int n = 0; n < 8; n++) {          // sw1: 2048 f4
            const int idx = tid + n * MTPB;
            const int r = idx >> 4, c = idx & 15;
            CP_ASYNC16(s1 + idx * 16, w1 + r * 1024 + mb * 64 + c * 4);
        }
        CP_COMMIT();
        #pragma unroll
        for (int n = 0; n < 16; n++) {         // sw2: 4096 f4
            const int idx = tid + n * MTPB;
            const int r = idx >> 2, c = idx & 3;
            CP_ASYNC16(s2 + idx * 16, w2 + r * 256 + mb * 16 + c * 4);
        }
        CP_COMMIT();
        #pragma unroll
        for (int n = 0; n < 8; n++) {          // sw3: 2048 f4
            const int idx = tid + n * MTPB;
            const int r = idx >> 3, c = idx & 7;
            CP_ASYNC16(s3 + idx * 16, w3 + r * 512 + mb * 32 + c * 4);
        }
        CP_COMMIT();
        #pragma unroll
        for (int n = 0; n < 4; n++) {          // sw4: 1024 f4
            const int idx = tid + n * MTPB;
            const int r = idx >> 1, c = idx & 1;
            CP_ASYNC16(s4 + idx * 16, w4 + r * 128 + mb * 8 + c * 4);
        }
        CP_COMMIT();
    }

    // ---- biases (independent of segsum) ----
    if (tid < 64) sm[OFF_B1 + tid] = b1[mb * 64 + tid];
    if (tid < 16) sm[OFF_B2 + tid] = b2[mb * 16 + tid];
    if (tid < 32) sm[OFF_B3 + tid] = b3[mb * 32 + tid];
    if (tid < 8)  sm[OFF_B4 + tid] = b4[mb * 8 + tid];

    // ---- PDL gate: wait for segsum's completion + memory visibility -------
    asm volatile("griddepcontrol.wait;" ::: "memory");

    // ---- pooled input: 1 float4/thread, padded stride ----
    {
        const float4 v = ((const float4*)g_sums)[tid];
        const int b = tid >> 5;
        const int m = tid & 31;
        const int cnt = cu[b + 1] - cu[b];
        const float c = 1.0f / (8.0f * (float)(cnt > 1 ? cnt : 1));
        float4 o; o.x = v.x * c; o.y = v.y * c; o.z = v.z * c; o.w = v.w * c;
        *(float4*)&stage[b * STR_POOL + m * 4] = o;
    }

    CP_WAIT(3);                                // sw1 ready (long since done)
    __syncthreads();

    // ===== L1: pooled(8x128) -> h1 (8 x 64 cols), silu ====================
    {
        const int cg = tid & 15, b = (tid >> 4) & 7, kc = tid >> 7;
        const float* hrow = &stage[b * STR_POOL + kc * 64];
        const float* wb   = &sw1[kc * 64 * 64 + cg * 4];
        float4 acc = make_float4(0.f, 0.f, 0.f, 0.f);
        #pragma unroll 4
        for (int k = 0; k < 64; k += 4) {
            const float4 hv = *(const float4*)&hrow[k];
            const float4 w0 = *(const float4*)&wb[(k + 0) * 64];
            const float4 wq1 = *(const float4*)&wb[(k + 1) * 64];
            const float4 wq2 = *(const float4*)&wb[(k + 2) * 64];
            const float4 wq3 = *(const float4*)&wb[(k + 3) * 64];
            FMA4X4(acc, hv, w0, wq1, wq2, wq3);
        }
        red4[tid] = acc;
        __syncthreads();
        if (tid < 128) {
            const float4 r0 = red4[tid];
            const float4 r1 = red4[tid + 128];
            const int jc = (tid & 15) * 4;
            float4 o;
            o.x = silu_f(r0.x + r1.x + sm[OFF_B1 + jc + 0]);
            o.y = silu_f(r0.y + r1.y + sm[OFF_B1 + jc + 1]);
            o.z = silu_f(r0.z + r1.z + sm[OFF_B1 + jc + 2]);
            o.w = silu_f(r0.w + r1.w + sm[OFF_B1 + jc + 3]);
            const int b_ = (tid >> 4) & 7;
            *(float4*)&g_h1[b_ * 1024 + mb * 64 + jc] = o;
        }
    }
    cluster_bar();                             // (1) h1 visible cluster-wide

    // ---- stage h1 (stride 1028) ----
    {
        const float4* src = (const float4*)g_h1;
        #pragma unroll
        for (int n = 0; n < 8; n++) {
            const int idx = tid + n * MTPB;    // 2048 f4
            const float4 v = src[idx];
            const int base = idx << 2;
            *(float4*)&stage[(base >> 10) * STR_H1 + (base & 1023)] = v;
        }
    }
    CP_WAIT(2);                                // sw2 ready
    __syncthreads();

    // ===== L2: h1 -> h2 (8 x 16 cols) =====================================
    {
        const int cg = tid & 3, b = (tid >> 2) & 7, kc = tid >> 5;
        const float* hrow = &stage[b * STR_H1 + kc * 128];
        const float* wb   = &sw2[kc * 128 * 16 + cg * 4];
        float4 acc = make_float4(0.f, 0.f, 0.f, 0.f);
        #pragma unroll 4
        for (int k = 0; k < 128; k += 4) {
            const float4 hv = *(const float4*)&hrow[k];
            const float4 w0 = *(const float4*)&wb[(k + 0) * 16];
            const float4 wq1 = *(const float4*)&wb[(k + 1) * 16];
            const float4 wq2 = *(const float4*)&wb[(k + 2) * 16];
            const float4 wq3 = *(const float4*)&wb[(k + 3) * 16];
            FMA4X4(acc, hv, w0, wq1, wq2, wq3);
        }
        red4[tid] = acc;
        __syncthreads();
        if (tid < 32) {
            float4 s = red4[tid];
            #pragma unroll
            for (int c = 1; c < 8; c++) {
                const float4 r = red4[tid + 32 * c];
                s.x += r.x; s.y += r.y; s.z += r.z; s.w += r.w;
            }
            const int jc = (tid & 3) * 4;
            const int b_ = tid >> 2;
            float4 o;
            o.x = s.x + sm[OFF_B2 + jc + 0];
            o.y = s.y + sm[OFF_B2 + jc + 1];
            o.z = s.z + sm[OFF_B2 + jc + 2];
            o.w = s.w + sm[OFF_B2 + jc + 3];
            *(float4*)&g_h2[b_ * 256 + mb * 16 + jc] = o;
        }
    }
    cluster_bar();                             // (2) h2 visible cluster-wide

    // ---- stage h2 (stride 260) ----
    {
        const float4* src = (const float4*)g_h2;
        #pragma unroll
        for (int n = 0; n < 2; n++) {
            const int idx = tid + n * MTPB;    // 512 f4
            const float4 v = src[idx];
            const int base = idx << 2;
            *(float4*)&stage[(base >> 8) * STR_H2 + (base & 255)] = v;
        }
    }
    CP_WAIT(1);                                // sw3 ready
    __syncthreads();

    // ===== L3: h2 -> h3 (8 x 32 cols), silu ===============================
    {
        const int cg = tid & 7, b = (tid >> 3) & 7, kc = tid >> 6;
        const float* hrow = &stage[b * STR_H2 + kc * 64];
        const float* wb   = &sw3[kc * 64 * 32 + cg * 4];
        float4 acc = make_float4(0.f, 0.f, 0.f, 0.f);
        #pragma unroll 4
        for (int k = 0; k < 64; k += 4) {
            const float4 hv = *(const float4*)&hrow[k];
            const float4 w0 = *(const float4*)&wb[(k + 0) * 32];
            const float4 wq1 = *(const float4*)&wb[(k + 1) * 32];
            const float4 wq2 = *(const float4*)&wb[(k + 2) * 32];
            const float4 wq3 = *(const float4*)&wb[(k + 3) * 32];
            FMA4X4(acc, hv, w0, wq1, wq2, wq3);
        }
        red4[tid] = acc;
        __syncthreads();
        if (tid < 64) {
            float4 s = red4[tid];
            #pragma unroll
            for (int c = 1; c < 4; c++) {
                const float4 r = red4[tid + 64 * c];
                s.x += r.x; s.y += r.y; s.z += r.z; s.w += r.w;
            }
            const int jc = (tid & 7) * 4;
            const int b_ = tid >> 3;
            float4 o;
            o.x = silu_f(s.x + sm[OFF_B3 + jc + 0]);
            o.y = silu_f(s.y + sm[OFF_B3 + jc + 1]);
            o.z = silu_f(s.z + sm[OFF_B3 + jc + 2]);
            o.w = silu_f(s.w + sm[OFF_B3 + jc + 3]);
            *(float4*)&g_h3[b_ * 512 + mb * 32 + jc] = o;
        }
    }
    cluster_bar();                             // (3) h3 visible cluster-wide

    // ---- stage h3 (stride 516) ----
    {
        const float4* src = (const float4*)g_h3;
        #pragma unroll
        for (int n = 0; n < 4; n++) {
            const int idx = tid + n * MTPB;    // 1024 f4
            const float4 v = src[idx];
            const int base = idx << 2;
            *(float4*)&stage[(base >> 9) * STR_H3 + (base & 511)] = v;
        }
    }
    CP_WAIT(0);                                // sw4 ready
    __syncthreads();

    // ===== L4: h3 -> h4 (8 x 8 cols), silu deferred =======================
    {
        const int cg = tid & 1, b = (tid >> 1) & 7, kc = tid >> 4;
        const float* hrow = &stage[b * STR_H3 + kc * 32];
        const float* wb   = &sw4[kc * 32 * 8 + cg * 4];
        float4 acc = make_float4(0.f, 0.f, 0.f, 0.f);
        #pragma unroll 4
        for (int k = 0; k < 32; k += 4) {
            const float4 hv = *(const float4*)&hrow[k];
            const float4 w0 = *(const float4*)&wb[(k + 0) * 8];
            const float4 wq1 = *(const float4*)&wb[(k + 1) * 8];
            const float4 wq2 = *(const float4*)&wb[(k + 2) * 8];
            const float4 wq3 = *(const float4*)&wb[(k + 3) * 8];
            FMA4X4(acc, hv, w0, wq1, wq2, wq3);
        }
        red4[tid] = acc;
        __syncthreads();
        if (tid < 16) {
            float4 s = red4[tid];
            #pragma unroll
            for (int c = 1; c < 16; c++) {
                const float4 r = red4[tid + 16 * c];
                s.x += r.x; s.y += r.y; s.z += r.z; s.w += r.w;
            }
            const int jc = (tid & 1) * 4;
            const int b_ = tid >> 1;
            float4 o;
            o.x = s.x + sm[OFF_B4 + jc + 0];
            o.y = s.y + sm[OFF_B4 + jc + 1];
            o.z = s.z + sm[OFF_B4 + jc + 2];
            o.w = s.w + sm[OFF_B4 + jc + 3];
            *(float4*)&g_h4[b_ * 128 + mb * 8 + jc] = o;
        }
    }

    // ===== Final barrier: blocks 1..15 arrive + exit; block 0 waits =======
    __threadfence();
    asm volatile("barrier.cluster.arrive.aligned;" ::: "memory");
    if (mb != 0) return;
    asm volatile("barrier.cluster.wait.aligned;" ::: "memory");

    // ===== L5 (block 0): logits + hard routing =============================
    {
        float* sred0 = stage;                  // [8][128]
        float* sred1 = stage + 1024;           // [8][128]
        const int k  = tid & 127;
        const int bh = tid >> 7;               // batches {bh, bh+2, bh+4, bh+6}
        const float wa = w5[k * 2 + 0];
        const float wb = w5[k * 2 + 1];

        __syncthreads();
        #pragma unroll
        for (int i = 0; i < 4; i++) {
            const int b = bh + 2 * i;
            const float s = silu_f(g_h4[b * 128 + k]);
            sred0[b * 128 + k] = s * wa;
            sred1[b * 128 + k] = s * wb;
        }
        __syncthreads();

        for (int off = 64; off >= 1; off >>= 1) {
            if (k < off) {
                #pragma unroll
                for (int i = 0; i < 4; i++) {
                    const int b = bh + 2 * i;
                    sred0[b * 128 + k] += sred0[b * 128 + k + off];
                    sred1[b * 128 + k] += sred1[b * 128 + k + off];
                }
            }
            __syncthreads();
        }

        if (k == 0) {
            const float bz0 = b5[0], bz1 = b5[1];
            #pragma unroll
            for (int i = 0; i < 4; i++) {
                const int b = bh + 2 * i;
                const float l0 = sred0[b * 128] + bz0;
                const float l1 = sred1[b * 128] + bz1;
                const float z  = (l1 > l0) ? 1.0f : 0.0f;
                #pragma unroll
                for (int h = 0; h < H_HEAD; h++)
                    out[b * H_HEAD + h] = z;
            }
        }
    }

    // ---- restore entry invariant for g_sums (block 0 only) ----------------
    __syncthreads();
    for (int i = tid; i < B_SEG * D_DIM; i += MTPB) g_sums[i] = 0.0f;
}

// ---------------------------------------------------------------------------
// Launch: 2 graph nodes, second with Programmatic Dependent Launch so its
// weight prefetch overlaps the first's 128 MB stream.
// ---------------------------------------------------------------------------
extern "C" void kernel_launch(void* const* d_in, const int* in_sizes, int n_in,
                              void* d_out, int out_size)
{
    const float* x  = (const float*)d_in[0];
    const int*   cu = (const int*)  d_in[1];
    const float* w1 = (const float*)d_in[2];
    const float* b1 = (const float*)d_in[3];
    const float* w2 = (const float*)d_in[4];
    const float* b2 = (const float*)d_in[5];
    const float* w3 = (const float*)d_in[6];
    const float* b3 = (const float*)d_in[7];
    const float* w4 = (const float*)d_in[8];
    const float* b4 = (const float*)d_in[9];
    const float* w5 = (const float*)d_in[10];
    const float* b5 = (const float*)d_in[11];
    float* out = (float*)d_out;

    cudaFuncSetAttribute(mlp_kernel,
                         cudaFuncAttributeMaxDynamicSharedMemorySize,
                         SMEM_MLP);
    cudaFuncSetAttribute(mlp_kernel,
                         cudaFuncAttributeNonPortableClusterSizeAllowed, 1);

    segsum_kernel<<<SBLK, STPB>>>((const float4*)x, cu);

    cudaLaunchConfig_t cfg = {};
    cfg.gridDim         = dim3(MBLK, 1, 1);
    cfg.blockDim        = dim3(MTPB, 1, 1);
    cfg.dynamicSmemBytes = SMEM_MLP;
    cudaLaunchAttribute attrs[1];
    attrs[0].id = cudaLaunchAttributeProgrammaticStreamSerialization;
    attrs[0].val.programmaticStreamSerializationAllowed = 1;
    cfg.attrs    = attrs;
    cfg.numAttrs = 1;
    cudaLaunchKernelEx(&cfg, mlp_kernel, cu, w1, b1, w2, b2, w3, b3,
                       w4, b4, w5, b5, out);
}